// round 5
// baseline (speedup 1.0000x reference)
#include <cuda_runtime.h>
#include <cstdint>

// ---------------------------------------------------------------------------
// NormEMAVectorQuantizer for GB300 (sm_103a via compute_103) — round 5
// TF32 mma.sync 2-way-split (3 products) + top-2 + exact-fp32 fixup.
//   out = concat( z_q[262144], loss[1], token_ids[8192],
//                 new_embedding[262144], new_cluster_sizes[8192] ) = 540673 f32
// ---------------------------------------------------------------------------

#define N_VEC   8192
#define N_TOK   8192
#define CDIM    32
#define KSPL    2

#define OFF_ZQ    0
#define OFF_LOSS  262144
#define OFF_TOK   262145
#define OFF_EMB   270337
#define OFF_CSZ   532481

// packed tf32 layout: per vector 68 uint32 = [hi 0..31 | lo 32..63 | pad 64..67]
#define NBW         68
#define CODE_BYTES  272
#define NB_CODES    128                       // codes per staging block
#define STAGE_BYTES (NB_CODES * CODE_BYTES)   // 34816
#define SMEM_TOTAL  (2 * STAGE_BYTES)         // 69632

// scratch (__device__ globals; no allocations allowed)
__device__ float              g_zn[N_VEC * CDIM];
__device__ uint32_t           g_qpk[N_VEC * NBW];
__device__ uint32_t           g_epk[N_TOK * NBW];
__device__ unsigned long long g_t1[KSPL * N_VEC];
__device__ unsigned long long g_t2[KSPL * N_VEC];
__device__ unsigned long long g_key[N_VEC];
__device__ int                g_fix[N_VEC];
__device__ int                g_nfix;
__device__ float              g_bins[N_TOK];
__device__ float              g_esum[N_TOK * CDIM];
__device__ float              g_loss;

// ---------------- helpers ---------------------------------------------------
static __device__ __forceinline__ uint32_t smem_u32(const void* p) {
    uint32_t a;
    asm("{ .reg .u64 t; cvta.to.shared.u64 t, %1; cvt.u32.u64 %0, t; }" : "=r"(a) : "l"(p));
    return a;
}
static __device__ __forceinline__ unsigned int ordered_u32(float v) {
    unsigned int b = __float_as_uint(v);
    return (b & 0x80000000u) ? ~b : (b | 0x80000000u);
}
static __device__ __forceinline__ float unordered_f32(unsigned int u) {
    unsigned int b = (u & 0x80000000u) ? (u & 0x7fffffffu) : ~u;
    return __uint_as_float(b);
}
static __device__ __forceinline__ void tf32_split(float x, uint32_t& hi, uint32_t& lo) {
    asm("cvt.rna.tf32.f32 %0, %1;" : "=r"(hi) : "f"(x));
    float r = x - __uint_as_float(hi);
    asm("cvt.rna.tf32.f32 %0, %1;" : "=r"(lo) : "f"(r));
}

#define MMA_TF32(D, Af, Bf)                                                   \
    asm volatile(                                                             \
        "mma.sync.aligned.m16n8k8.row.col.f32.tf32.tf32.f32 "                 \
        "{%0,%1,%2,%3}, {%4,%5,%6,%7}, {%8,%9}, {%0,%1,%2,%3};"               \
        : "+f"((D)[0]), "+f"((D)[1]), "+f"((D)[2]), "+f"((D)[3])              \
        : "r"((Af)[0]), "r"((Af)[1]), "r"((Af)[2]), "r"((Af)[3]),             \
          "r"((Bf)[0]), "r"((Bf)[1]))

// ---------------------------------------------------------------------------
// K1: prep — L2norm(z)->g_zn + tf32 hi/lo pack; embedding tf32 pack; zeroing
// ---------------------------------------------------------------------------
#define NORM_BLKS 1024
#define ESPL_BLKS 1024
#define ZERO_ITEMS (N_TOK * CDIM + N_TOK)
#define ZERO_BLKS ((ZERO_ITEMS + 255) / 256)

__global__ __launch_bounds__(256) void k_prep(const float* __restrict__ z,
                                              const float* __restrict__ emb) {
    if (blockIdx.x < NORM_BLKS) {
        int warp = threadIdx.x >> 5;
        int lane = threadIdx.x & 31;                 // channel c
        int n    = blockIdx.x * 8 + warp;
        int b    = n >> 8, hw = n & 255;
        float v  = z[b * (CDIM * 256) + lane * 256 + hw];
        float ss = v * v;
#pragma unroll
        for (int o = 16; o > 0; o >>= 1)
            ss += __shfl_xor_sync(0xffffffffu, ss, o);
        float inv = 1.0f / fmaxf(sqrtf(ss), 1e-12f);
        float x = v * inv;
        g_zn[n * CDIM + lane] = x;
        uint32_t hi, lo;
        tf32_split(x, hi, lo);
        g_qpk[n * NBW + lane]      = hi;
        g_qpk[n * NBW + 32 + lane] = lo;
    } else if (blockIdx.x < NORM_BLKS + ESPL_BLKS) {
        int i = (blockIdx.x - NORM_BLKS) * 256 + threadIdx.x;   // 0..262143
        int r = i >> 5, c = i & 31;
        uint32_t hi, lo;
        tf32_split(emb[i], hi, lo);
        g_epk[r * NBW + c]      = hi;
        g_epk[r * NBW + 32 + c] = lo;
    } else {
        int i = (blockIdx.x - NORM_BLKS - ESPL_BLKS) * 256 + threadIdx.x;
        if (i < N_TOK * CDIM) g_esum[i] = 0.0f;
        else if (i < ZERO_ITEMS) g_bins[i - N_TOK * CDIM] = 0.0f;
        if (i == 0) { g_loss = 0.0f; g_nfix = 0; }
    }
}

// ---------------------------------------------------------------------------
// K2: TF32 mma.sync similarity + fused top-2 argmax.
// grid (128, 2), 128 threads (4 warps). Warp = 16 queries; CTA = 64 queries
// x 4096 codes (k-split). B staged via cp.async double buffer.
// ---------------------------------------------------------------------------
__global__ __launch_bounds__(128) void k_mma() {
    extern __shared__ uint32_t smem[];
    uint32_t sbase = smem_u32(smem);
    int tid = threadIdx.x, wid = tid >> 5, lane = tid & 31;
    int g4 = lane >> 2, l4 = lane & 3;
    int qb    = blockIdx.x * 64 + wid * 16;
    int kbase = blockIdx.y * (N_TOK / KSPL);

    // A fragments: [split][kchunk][a0..a3], resident whole kernel (32 regs)
    uint32_t A[2][4][4];
    {
        const uint32_t* q0 = g_qpk + (qb + g4) * NBW;
        const uint32_t* q8 = g_qpk + (qb + g4 + 8) * NBW;
#pragma unroll
        for (int s = 0; s < 2; s++)
#pragma unroll
            for (int kc = 0; kc < 4; kc++) {
                int w = s * 32 + kc * 8 + l4;
                A[s][kc][0] = q0[w];
                A[s][kc][1] = q8[w];
                A[s][kc][2] = q0[w + 4];
                A[s][kc][3] = q8[w + 4];
            }
    }

    unsigned long long k1a = 0, k2a = 0, k1b = 0, k2b = 0;

    // prefetch block 0
    {
        const char* src = (const char*)g_epk + (size_t)kbase * CODE_BYTES;
#pragma unroll
        for (int j = 0; j < 17; j++) {
            int idx = tid + j * 128;
            asm volatile("cp.async.ca.shared.global [%0], [%1], 16;"
                         :: "r"(sbase + idx * 16), "l"(src + idx * 16) : "memory");
        }
        asm volatile("cp.async.commit_group;" ::: "memory");
    }

    for (int nb = 0; nb < (N_TOK / KSPL) / NB_CODES; nb++) {
        asm volatile("cp.async.wait_group 0;" ::: "memory");
        __syncthreads();
        if (nb + 1 < (N_TOK / KSPL) / NB_CODES) {
            const char* src = (const char*)g_epk +
                              (size_t)(kbase + (nb + 1) * NB_CODES) * CODE_BYTES;
            uint32_t dst = sbase + ((nb + 1) & 1) * STAGE_BYTES;
#pragma unroll
            for (int j = 0; j < 17; j++) {
                int idx = tid + j * 128;
                asm volatile("cp.async.ca.shared.global [%0], [%1], 16;"
                             :: "r"(dst + idx * 16), "l"(src + idx * 16) : "memory");
            }
            asm volatile("cp.async.commit_group;" ::: "memory");
        }

        const uint32_t* buf = smem + (nb & 1) * (STAGE_BYTES / 4);

#pragma unroll 1
        for (int nt = 0; nt < NB_CODES / 8; nt += 2) {
            // B fragments for two n-tiles (codes nt*8+g4 and (nt+1)*8+g4)
            const uint32_t* r0 = buf + (nt * 8 + g4) * NBW;
            const uint32_t* r1 = r0 + 8 * NBW;
            uint32_t B0[2][4][2], B1[2][4][2];
#pragma unroll
            for (int s = 0; s < 2; s++)
#pragma unroll
                for (int kc = 0; kc < 4; kc++) {
                    int w = s * 32 + kc * 8 + l4;
                    B0[s][kc][0] = r0[w];  B0[s][kc][1] = r0[w + 4];
                    B1[s][kc][0] = r1[w];  B1[s][kc][1] = r1[w + 4];
                }

            float D0[4] = {0.f, 0.f, 0.f, 0.f};
            float D1[4] = {0.f, 0.f, 0.f, 0.f};
#pragma unroll
            for (int kc = 0; kc < 4; kc++) { MMA_TF32(D0, A[0][kc], B0[0][kc]);
                                             MMA_TF32(D1, A[0][kc], B1[0][kc]); }
#pragma unroll
            for (int kc = 0; kc < 4; kc++) { MMA_TF32(D0, A[0][kc], B0[1][kc]);
                                             MMA_TF32(D1, A[0][kc], B1[1][kc]); }
#pragma unroll
            for (int kc = 0; kc < 4; kc++) { MMA_TF32(D0, A[1][kc], B0[0][kc]);
                                             MMA_TF32(D1, A[1][kc], B1[0][kc]); }

            int c0 = kbase + nb * NB_CODES + nt * 8 + l4 * 2;
#define UPD(x1, x2, v, k) {                                                   \
            unsigned long long _key =                                         \
                ((unsigned long long)ordered_u32(v) << 32) |                  \
                (unsigned int)(N_TOK - 1 - (k));                              \
            if (_key > (x1)) { (x2) = (x1); (x1) = _key; }                    \
            else if (_key > (x2)) (x2) = _key; }
            UPD(k1a, k2a, D0[0], c0);     UPD(k1a, k2a, D0[1], c0 + 1);
            UPD(k1b, k2b, D0[2], c0);     UPD(k1b, k2b, D0[3], c0 + 1);
            UPD(k1a, k2a, D1[0], c0 + 8); UPD(k1a, k2a, D1[1], c0 + 9);
            UPD(k1b, k2b, D1[2], c0 + 8); UPD(k1b, k2b, D1[3], c0 + 9);
#undef UPD
        }
    }

    // reduce top-2 across the 4 lanes sharing a row group (l4 = 0..3)
#pragma unroll
    for (int d = 1; d < 4; d <<= 1) {
        unsigned long long o1, o2, mn, mx2;
        o1 = __shfl_xor_sync(0xffffffffu, k1a, d);
        o2 = __shfl_xor_sync(0xffffffffu, k2a, d);
        mn = k1a < o1 ? k1a : o1;
        k1a = k1a > o1 ? k1a : o1;
        mx2 = k2a > o2 ? k2a : o2;
        k2a = mn > mx2 ? mn : mx2;
        o1 = __shfl_xor_sync(0xffffffffu, k1b, d);
        o2 = __shfl_xor_sync(0xffffffffu, k2b, d);
        mn = k1b < o1 ? k1b : o1;
        k1b = k1b > o1 ? k1b : o1;
        mx2 = k2b > o2 ? k2b : o2;
        k2b = mn > mx2 ? mn : mx2;
    }
    if (l4 == 0) {
        int q = qb + g4;
        g_t1[blockIdx.y * N_VEC + q]     = k1a;
        g_t2[blockIdx.y * N_VEC + q]     = k2a;
        g_t1[blockIdx.y * N_VEC + q + 8] = k1b;
        g_t2[blockIdx.y * N_VEC + q + 8] = k2b;
    }
}

// ---------------------------------------------------------------------------
// K3: merge the two k-splits' top-2, write key, flag tiny-gap queries
// ---------------------------------------------------------------------------
__global__ __launch_bounds__(256) void k_merge() {
    int n = blockIdx.x * 256 + threadIdx.x;
    unsigned long long a1 = g_t1[n], a2 = g_t2[n];
    unsigned long long b1 = g_t1[N_VEC + n], b2 = g_t2[N_VEC + n];
    unsigned long long n1 = a1 > b1 ? a1 : b1;
    unsigned long long mn = a1 < b1 ? a1 : b1;
    unsigned long long mx2 = a2 > b2 ? a2 : b2;
    unsigned long long n2 = mn > mx2 ? mn : mx2;
    g_key[n] = n1;
    float v1 = unordered_f32((unsigned int)(n1 >> 32));
    float v2 = unordered_f32((unsigned int)(n2 >> 32));
    if (v1 - v2 < 4e-6f) {
        int i = atomicAdd(&g_nfix, 1);
        g_fix[i] = n;
    }
}

// ---------------------------------------------------------------------------
// K4: exact fp32 rescan for flagged queries (CTA per query)
// ---------------------------------------------------------------------------
__global__ __launch_bounds__(256) void k_fixup(const float* __restrict__ emb) {
    __shared__ float zq[CDIM];
    __shared__ unsigned long long red[8];
    int cnt = g_nfix;
    for (int f = blockIdx.x; f < cnt; f += gridDim.x) {
        int n = g_fix[f];
        if (threadIdx.x < CDIM) zq[threadIdx.x] = g_zn[n * CDIM + threadIdx.x];
        __syncthreads();
        unsigned long long best = 0;
        int t = threadIdx.x;
        for (int k = t * 32; k < t * 32 + 32; k++) {
            const float* e = emb + k * CDIM;
            float s = 0.0f;
#pragma unroll
            for (int c = 0; c < CDIM; c++) s = fmaf(zq[c], e[c], s);
            unsigned long long key =
                ((unsigned long long)ordered_u32(s) << 32) |
                (unsigned int)(N_TOK - 1 - k);
            if (key > best) best = key;
        }
#pragma unroll
        for (int o = 16; o > 0; o >>= 1) {
            unsigned long long ov = __shfl_xor_sync(0xffffffffu, best, o);
            if (ov > best) best = ov;
        }
        if ((t & 31) == 0) red[t >> 5] = best;
        __syncthreads();
        if (t == 0) {
            unsigned long long b = red[0];
#pragma unroll
            for (int w = 1; w < 8; w++) if (red[w] > b) b = red[w];
            g_key[n] = b;
        }
        __syncthreads();
    }
}

// ---------------------------------------------------------------------------
// K5: scatter epilogue over 262144 threads
// ---------------------------------------------------------------------------
__global__ __launch_bounds__(256) void k_scatter(const float* __restrict__ emb,
                                                 float* __restrict__ out) {
    __shared__ float red[8];
    int g  = blockIdx.x * 256 + threadIdx.x;
    int b  = g >> 13;
    int c  = (g >> 8) & 31;
    int hw = g & 255;
    int n  = b * 256 + hw;

    unsigned long long key = g_key[n];
    int bi = (N_TOK - 1) - (int)(unsigned int)(key & 0xffffffffu);

    float ev = emb[bi * CDIM + c];
    float zv = g_zn[n * CDIM + c];
    out[OFF_ZQ + g] = ev;
    if (c == 0) {
        out[OFF_TOK + n] = (float)bi;
        atomicAdd(&g_bins[bi], 1.0f);
    }
    atomicAdd(&g_esum[bi * CDIM + c], zv);

    float d = ev - zv;
    float lsum = d * d;
#pragma unroll
    for (int o = 16; o > 0; o >>= 1)
        lsum += __shfl_xor_sync(0xffffffffu, lsum, o);
    if ((threadIdx.x & 31) == 0) red[threadIdx.x >> 5] = lsum;
    __syncthreads();
    if (threadIdx.x == 0) {
        float s = 0.0f;
#pragma unroll
        for (int w = 0; w < 8; w++) s += red[w];
        atomicAdd(&g_loss, s);
    }
}

// ---------------------------------------------------------------------------
// K6: EMA codebook update + loss write
// ---------------------------------------------------------------------------
__global__ __launch_bounds__(256) void k_update(const float* __restrict__ emb,
                                                const float* __restrict__ csz,
                                                float* __restrict__ out) {
    int gtid = blockIdx.x * 256 + threadIdx.x;
    int k    = gtid >> 5;
    int lane = gtid & 31;

    float bcount = g_bins[k];
    if (lane == 0)
        out[OFF_CSZ + k] = csz[k] * 0.99f + 0.01f * bcount;

    bool  zero = (bcount == 0.0f);
    float bc   = zero ? 1.0f : bcount;
    float m    = g_esum[k * CDIM + lane] / bc;
    float ss   = m * m;
#pragma unroll
    for (int o = 16; o > 0; o >>= 1)
        ss += __shfl_xor_sync(0xffffffffu, ss, o);
    float en = m / fmaxf(sqrtf(ss), 1e-12f);

    float ev = emb[k * CDIM + lane];
    if (zero) en = ev;
    float v  = ev * 0.99f + 0.01f * en;
    float s2 = v * v;
#pragma unroll
    for (int o = 16; o > 0; o >>= 1)
        s2 += __shfl_xor_sync(0xffffffffu, s2, o);
    out[OFF_EMB + k * CDIM + lane] = v / fmaxf(sqrtf(s2), 1e-12f);

    if (gtid == 0)
        out[OFF_LOSS] = g_loss * (1.0f / (float)(N_VEC * CDIM));
}

// ---------------------------------------------------------------------------
extern "C" void kernel_launch(void* const* d_in, const int* in_sizes, int n_in,
                              void* d_out, int out_size) {
    const float* z   = (const float*)d_in[0];
    const float* emb = (const float*)d_in[1];
    const float* csz = (const float*)d_in[2];
    float* out = (float*)d_out;

    cudaFuncSetAttribute(k_mma, cudaFuncAttributeMaxDynamicSharedMemorySize, SMEM_TOTAL);

    k_prep<<<NORM_BLKS + ESPL_BLKS + ZERO_BLKS, 256>>>(z, emb);
    dim3 grid_mma(N_VEC / 64, KSPL);
    k_mma<<<grid_mma, 128, SMEM_TOTAL>>>();
    k_merge<<<N_VEC / 256, 256>>>();
    k_fixup<<<64, 256>>>(emb);
    k_scatter<<<(N_VEC * CDIM) / 256, 256>>>(emb, out);
    k_update<<<(N_TOK * CDIM) / 256, 256>>>(emb, csz, out);
}

// round 6
// speedup vs baseline: 1.5810x; 1.5810x over previous
#include <cuda_runtime.h>
#include <cstdint>

// ---------------------------------------------------------------------------
// NormEMAVectorQuantizer (sm_103a via compute_103) — round 6
// Plain-TF32 mma.sync screen (1 product) + top-2 gap test + exact fp32 fixup.
//   out = concat( z_q[262144], loss[1], token_ids[8192],
//                 new_embedding[262144], new_cluster_sizes[8192] ) = 540673 f32
// ---------------------------------------------------------------------------

#define N_VEC   8192
#define N_TOK   8192
#define CDIM    32
#define KSPL    2
#define THRESH  2.0e-3f     // >= 2 * (2^-10) rigorous tf32 dot-error bound

#define OFF_ZQ    0
#define OFF_LOSS  262144
#define OFF_TOK   262145
#define OFF_EMB   270337
#define OFF_CSZ   532481

// B layout: per code 36 words (32 tf32 hi, fragment-pair reordered, +4 pad)
#define EPKW        36
#define CODE_BYTES  144
#define NB_CODES    128
#define STAGE_BYTES (NB_CODES * CODE_BYTES)   // 18432
#define SMEM_TOTAL  (2 * STAGE_BYTES)         // 36864

// scratch (__device__ globals; no allocations allowed)
__device__ float              g_zn[N_VEC * CDIM];
__device__ uint32_t           g_qpk[N_VEC * CDIM];     // tf32 hi, dense
__device__ uint32_t           g_epk[N_TOK * EPKW];     // tf32 hi, reordered
__device__ unsigned long long g_t1[KSPL * N_VEC];      // packed (val|inv idx)
__device__ float              g_t2v[KSPL * N_VEC];     // runner-up value
__device__ unsigned long long g_key[N_VEC];
__device__ int                g_fix[N_VEC];
__device__ int                g_nfix;
__device__ float              g_bins[N_TOK];
__device__ float              g_esum[N_TOK * CDIM];
__device__ float              g_loss;

// ---------------- helpers ---------------------------------------------------
static __device__ __forceinline__ uint32_t smem_u32(const void* p) {
    uint32_t a;
    asm("{ .reg .u64 t; cvta.to.shared.u64 t, %1; cvt.u32.u64 %0, t; }" : "=r"(a) : "l"(p));
    return a;
}
static __device__ __forceinline__ unsigned int ordered_u32(float v) {
    unsigned int b = __float_as_uint(v);
    return (b & 0x80000000u) ? ~b : (b | 0x80000000u);
}
static __device__ __forceinline__ float unordered_f32(unsigned int u) {
    unsigned int b = (u & 0x80000000u) ? (u & 0x7fffffffu) : ~u;
    return __uint_as_float(b);
}
static __device__ __forceinline__ uint32_t to_tf32(float x) {
    uint32_t r;
    asm("cvt.rna.tf32.f32 %0, %1;" : "=r"(r) : "f"(x));
    return r;
}
// reorder word c (0..31) of a code row so B-fragment pairs are adjacent:
// pos = kc*8 + (c%8<4 ? (c%8)*2 : (c%8-4)*2+1)
static __device__ __forceinline__ int b_reorder(int c) {
    int kc = c >> 3, r = c & 7;
    return kc * 8 + ((r < 4) ? (r * 2) : ((r - 4) * 2 + 1));
}

#define MMA_TF32(D, Af, Bf)                                                   \
    asm volatile(                                                             \
        "mma.sync.aligned.m16n8k8.row.col.f32.tf32.tf32.f32 "                 \
        "{%0,%1,%2,%3}, {%4,%5,%6,%7}, {%8,%9}, {%0,%1,%2,%3};"               \
        : "+f"((D)[0]), "+f"((D)[1]), "+f"((D)[2]), "+f"((D)[3])              \
        : "r"((Af)[0]), "r"((Af)[1]), "r"((Af)[2]), "r"((Af)[3]),             \
          "r"((Bf)[0]), "r"((Bf)[1]))

// ---------------------------------------------------------------------------
// K1: prep — L2norm(z)->g_zn + tf32 pack; embedding tf32 reorder-pack; zero
// ---------------------------------------------------------------------------
#define NORM_BLKS 1024
#define ESPL_BLKS 1024
#define ZERO_ITEMS (N_TOK * CDIM + N_TOK)
#define ZERO_BLKS ((ZERO_ITEMS + 255) / 256)

__global__ __launch_bounds__(256) void k_prep(const float* __restrict__ z,
                                              const float* __restrict__ emb) {
    if (blockIdx.x < NORM_BLKS) {
        int warp = threadIdx.x >> 5;
        int lane = threadIdx.x & 31;                 // channel c
        int n    = blockIdx.x * 8 + warp;
        int b    = n >> 8, hw = n & 255;
        float v  = z[b * (CDIM * 256) + lane * 256 + hw];
        float ss = v * v;
#pragma unroll
        for (int o = 16; o > 0; o >>= 1)
            ss += __shfl_xor_sync(0xffffffffu, ss, o);
        float inv = 1.0f / fmaxf(sqrtf(ss), 1e-12f);
        float x = v * inv;
        g_zn[n * CDIM + lane]  = x;
        g_qpk[n * CDIM + lane] = to_tf32(x);
    } else if (blockIdx.x < NORM_BLKS + ESPL_BLKS) {
        int i = (blockIdx.x - NORM_BLKS) * 256 + threadIdx.x;   // 0..262143
        int r = i >> 5, c = i & 31;
        g_epk[r * EPKW + b_reorder(c)] = to_tf32(emb[i]);
    } else {
        int i = (blockIdx.x - NORM_BLKS - ESPL_BLKS) * 256 + threadIdx.x;
        if (i < N_TOK * CDIM) g_esum[i] = 0.0f;
        else if (i < ZERO_ITEMS) g_bins[i - N_TOK * CDIM] = 0.0f;
        if (i == 0) { g_loss = 0.0f; g_nfix = 0; }
    }
}

// ---------------------------------------------------------------------------
// K2: TF32 mma.sync screen + fused top-2.
// grid (64, 2), 256 threads (8 warps). Warp = 16 queries; CTA = 128 queries
// x 4096 codes. B staged via cp.async double buffer (hi only).
// ---------------------------------------------------------------------------
__global__ __launch_bounds__(256) void k_mma() {
    extern __shared__ uint32_t smem[];
    uint32_t sbase = smem_u32(smem);
    int tid = threadIdx.x, wid = tid >> 5, lane = tid & 31;
    int g4 = lane >> 2, l4 = lane & 3;
    int qb    = blockIdx.x * 128 + wid * 16;
    int kbase = blockIdx.y * (N_TOK / KSPL);

    // A fragments (16 regs), resident whole kernel
    uint32_t A[4][4];
    {
        const uint32_t* q0 = g_qpk + (qb + g4) * CDIM;
        const uint32_t* q8 = g_qpk + (qb + g4 + 8) * CDIM;
#pragma unroll
        for (int kc = 0; kc < 4; kc++) {
            int w = kc * 8 + l4;
            A[kc][0] = q0[w];
            A[kc][1] = q8[w];
            A[kc][2] = q0[w + 4];
            A[kc][3] = q8[w + 4];
        }
    }

    // top-2 state for the two query rows this thread touches (g4 and g4+8)
    float v1a = -3.4e38f, v2a = -3.4e38f; int k1a = 0;
    float v1b = -3.4e38f, v2b = -3.4e38f; int k1b = 0;

    // prefetch block 0
    {
        const char* src = (const char*)g_epk + (size_t)kbase * CODE_BYTES;
#pragma unroll
        for (int j = 0; j < 5; j++) {
            int idx = tid + j * 256;
            if (idx < STAGE_BYTES / 16)
                asm volatile("cp.async.ca.shared.global [%0], [%1], 16;"
                             :: "r"(sbase + idx * 16), "l"(src + idx * 16) : "memory");
        }
        asm volatile("cp.async.commit_group;" ::: "memory");
    }

    for (int nb = 0; nb < (N_TOK / KSPL) / NB_CODES; nb++) {
        asm volatile("cp.async.wait_group 0;" ::: "memory");
        __syncthreads();
        if (nb + 1 < (N_TOK / KSPL) / NB_CODES) {
            const char* src = (const char*)g_epk +
                              (size_t)(kbase + (nb + 1) * NB_CODES) * CODE_BYTES;
            uint32_t dst = sbase + ((nb + 1) & 1) * STAGE_BYTES;
#pragma unroll
            for (int j = 0; j < 5; j++) {
                int idx = tid + j * 256;
                if (idx < STAGE_BYTES / 16)
                    asm volatile("cp.async.ca.shared.global [%0], [%1], 16;"
                                 :: "r"(dst + idx * 16), "l"(src + idx * 16) : "memory");
            }
            asm volatile("cp.async.commit_group;" ::: "memory");
        }

        const uint32_t* buf = smem + (nb & 1) * (STAGE_BYTES / 4);

#pragma unroll 1
        for (int nt = 0; nt < NB_CODES / 8; nt += 2) {
            const uint32_t* r0 = buf + (nt * 8 + g4) * EPKW + l4 * 2;
            const uint32_t* r1 = r0 + 8 * EPKW;
            float D0[4] = {0.f, 0.f, 0.f, 0.f};
            float D1[4] = {0.f, 0.f, 0.f, 0.f};
#pragma unroll
            for (int kc = 0; kc < 4; kc++) {
                uint2 b0 = *(const uint2*)(r0 + kc * 8);
                uint2 b1 = *(const uint2*)(r1 + kc * 8);
                uint32_t B0[2] = {b0.x, b0.y};
                uint32_t B1[2] = {b1.x, b1.y};
                MMA_TF32(D0, A[kc], B0);
                MMA_TF32(D1, A[kc], B1);
            }

            int c0 = kbase + nb * NB_CODES + nt * 8 + l4 * 2;
#define UPD(v1, v2, k1, v, k)                                                 \
            { float _v = (v);                                                 \
              if (_v > (v1)) { (v2) = (v1); (v1) = _v; (k1) = (k); }          \
              else (v2) = fmaxf((v2), _v); }
            UPD(v1a, v2a, k1a, D0[0], c0);     UPD(v1a, v2a, k1a, D0[1], c0 + 1);
            UPD(v1b, v2b, k1b, D0[2], c0);     UPD(v1b, v2b, k1b, D0[3], c0 + 1);
            UPD(v1a, v2a, k1a, D1[0], c0 + 8); UPD(v1a, v2a, k1a, D1[1], c0 + 9);
            UPD(v1b, v2b, k1b, D1[2], c0 + 8); UPD(v1b, v2b, k1b, D1[3], c0 + 9);
#undef UPD
        }
    }

    // reduce top-2 across the 4 lanes of each row group (xor 1, 2)
#pragma unroll
    for (int d = 1; d < 4; d <<= 1) {
        float ov1; int ok1; float ov2;
        ov1 = __shfl_xor_sync(0xffffffffu, v1a, d);
        ok1 = __shfl_xor_sync(0xffffffffu, k1a, d);
        ov2 = __shfl_xor_sync(0xffffffffu, v2a, d);
        {
            bool take = (ov1 > v1a) || (ov1 == v1a && ok1 < k1a);
            float lose = take ? v1a : ov1;
            v2a = fmaxf(fmaxf(v2a, ov2), lose);
            if (take) { v1a = ov1; k1a = ok1; }
        }
        ov1 = __shfl_xor_sync(0xffffffffu, v1b, d);
        ok1 = __shfl_xor_sync(0xffffffffu, k1b, d);
        ov2 = __shfl_xor_sync(0xffffffffu, v2b, d);
        {
            bool take = (ov1 > v1b) || (ov1 == v1b && ok1 < k1b);
            float lose = take ? v1b : ov1;
            v2b = fmaxf(fmaxf(v2b, ov2), lose);
            if (take) { v1b = ov1; k1b = ok1; }
        }
    }
    if (l4 == 0) {
        int q = qb + g4;
        int sp = blockIdx.y;
        g_t1[sp * N_VEC + q] =
            ((unsigned long long)ordered_u32(v1a) << 32) |
            (unsigned int)(N_TOK - 1 - k1a);
        g_t2v[sp * N_VEC + q] = v2a;
        g_t1[sp * N_VEC + q + 8] =
            ((unsigned long long)ordered_u32(v1b) << 32) |
            (unsigned int)(N_TOK - 1 - k1b);
        g_t2v[sp * N_VEC + q + 8] = v2b;
    }
}

// ---------------------------------------------------------------------------
// K3: merge splits, gap test, build fixup list
// ---------------------------------------------------------------------------
__global__ __launch_bounds__(256) void k_merge() {
    int n = blockIdx.x * 256 + threadIdx.x;
    unsigned long long a = g_t1[n], b = g_t1[N_VEC + n];
    unsigned long long win = a > b ? a : b;
    unsigned long long lose = a > b ? b : a;
    float v2 = fmaxf(fmaxf(g_t2v[n], g_t2v[N_VEC + n]),
                     unordered_f32((unsigned int)(lose >> 32)));
    float v1 = unordered_f32((unsigned int)(win >> 32));
    if (v1 - v2 < THRESH) {
        g_key[n] = 0ull;                 // exact pass will atomicMax real keys
        int i = atomicAdd(&g_nfix, 1);
        g_fix[i] = n;
    } else {
        g_key[n] = win;
    }
}

// ---------------------------------------------------------------------------
// K4: exact fp32 rescan for flagged queries.
// grid 1024 x 128 threads: block = (query slot f, code chunk of 1024);
// thread = 8 codes (coalesced-ish float4 rows from L2). atomicMax merge.
// ---------------------------------------------------------------------------
__global__ __launch_bounds__(128) void k_fixup(const float* __restrict__ emb) {
    __shared__ float zq[CDIM];
    __shared__ unsigned long long red[4];
    int cnt = g_nfix;
    int chunk = blockIdx.x & 7;
    int t = threadIdx.x;
    for (int f = blockIdx.x >> 3; f < cnt; f += 128) {
        int n = g_fix[f];
        if (t < CDIM) zq[t] = g_zn[n * CDIM + t];
        __syncthreads();
        unsigned long long best = 0;
#pragma unroll 1
        for (int j = 0; j < 8; j++) {
            int k = chunk * 1024 + j * 128 + t;
            const float4* e = (const float4*)(emb + k * CDIM);
            float s = 0.0f;
#pragma unroll
            for (int q4 = 0; q4 < 8; q4++) {
                float4 ev = e[q4];
                s = fmaf(zq[q4 * 4 + 0], ev.x, s);
                s = fmaf(zq[q4 * 4 + 1], ev.y, s);
                s = fmaf(zq[q4 * 4 + 2], ev.z, s);
                s = fmaf(zq[q4 * 4 + 3], ev.w, s);
            }
            unsigned long long key =
                ((unsigned long long)ordered_u32(s) << 32) |
                (unsigned int)(N_TOK - 1 - k);
            if (key > best) best = key;
        }
#pragma unroll
        for (int o = 16; o > 0; o >>= 1) {
            unsigned long long ov = __shfl_xor_sync(0xffffffffu, best, o);
            if (ov > best) best = ov;
        }
        if ((t & 31) == 0) red[t >> 5] = best;
        __syncthreads();
        if (t == 0) {
            unsigned long long b = red[0];
#pragma unroll
            for (int w = 1; w < 4; w++) if (red[w] > b) b = red[w];
            atomicMax(&g_key[n], b);
        }
        __syncthreads();
    }
}

// ---------------------------------------------------------------------------
// K5: scatter epilogue over 262144 threads
// ---------------------------------------------------------------------------
__global__ __launch_bounds__(256) void k_scatter(const float* __restrict__ emb,
                                                 float* __restrict__ out) {
    __shared__ float red[8];
    int g  = blockIdx.x * 256 + threadIdx.x;
    int b  = g >> 13;
    int c  = (g >> 8) & 31;
    int hw = g & 255;
    int n  = b * 256 + hw;

    unsigned long long key = g_key[n];
    int bi = (N_TOK - 1) - (int)(unsigned int)(key & 0xffffffffu);

    float ev = emb[bi * CDIM + c];
    float zv = g_zn[n * CDIM + c];
    out[OFF_ZQ + g] = ev;
    if (c == 0) {
        out[OFF_TOK + n] = (float)bi;
        atomicAdd(&g_bins[bi], 1.0f);
    }
    atomicAdd(&g_esum[bi * CDIM + c], zv);

    float d = ev - zv;
    float lsum = d * d;
#pragma unroll
    for (int o = 16; o > 0; o >>= 1)
        lsum += __shfl_xor_sync(0xffffffffu, lsum, o);
    if ((threadIdx.x & 31) == 0) red[threadIdx.x >> 5] = lsum;
    __syncthreads();
    if (threadIdx.x == 0) {
        float s = 0.0f;
#pragma unroll
        for (int w = 0; w < 8; w++) s += red[w];
        atomicAdd(&g_loss, s);
    }
}

// ---------------------------------------------------------------------------
// K6: EMA codebook update + loss write
// ---------------------------------------------------------------------------
__global__ __launch_bounds__(256) void k_update(const float* __restrict__ emb,
                                                const float* __restrict__ csz,
                                                float* __restrict__ out) {
    int gtid = blockIdx.x * 256 + threadIdx.x;
    int k    = gtid >> 5;
    int lane = gtid & 31;

    float bcount = g_bins[k];
    if (lane == 0)
        out[OFF_CSZ + k] = csz[k] * 0.99f + 0.01f * bcount;

    bool  zero = (bcount == 0.0f);
    float bc   = zero ? 1.0f : bcount;
    float m    = g_esum[k * CDIM + lane] / bc;
    float ss   = m * m;
#pragma unroll
    for (int o = 16; o > 0; o >>= 1)
        ss += __shfl_xor_sync(0xffffffffu, ss, o);
    float en = m / fmaxf(sqrtf(ss), 1e-12f);

    float ev = emb[k * CDIM + lane];
    if (zero) en = ev;
    float v  = ev * 0.99f + 0.01f * en;
    float s2 = v * v;
#pragma unroll
    for (int o = 16; o > 0; o >>= 1)
        s2 += __shfl_xor_sync(0xffffffffu, s2, o);
    out[OFF_EMB + k * CDIM + lane] = v / fmaxf(sqrtf(s2), 1e-12f);

    if (gtid == 0)
        out[OFF_LOSS] = g_loss * (1.0f / (float)(N_VEC * CDIM));
}

// ---------------------------------------------------------------------------
extern "C" void kernel_launch(void* const* d_in, const int* in_sizes, int n_in,
                              void* d_out, int out_size) {
    const float* z   = (const float*)d_in[0];
    const float* emb = (const float*)d_in[1];
    const float* csz = (const float*)d_in[2];
    float* out = (float*)d_out;

    cudaFuncSetAttribute(k_mma, cudaFuncAttributeMaxDynamicSharedMemorySize, SMEM_TOTAL);

    k_prep<<<NORM_BLKS + ESPL_BLKS + ZERO_BLKS, 256>>>(z, emb);
    dim3 grid_mma(N_VEC / 128, KSPL);
    k_mma<<<grid_mma, 256, SMEM_TOTAL>>>();
    k_merge<<<N_VEC / 256, 256>>>();
    k_fixup<<<1024, 128>>>(emb);
    k_scatter<<<(N_VEC * CDIM) / 256, 256>>>(emb, out);
    k_update<<<(N_TOK * CDIM) / 256, 256>>>(emb, csz, out);
}

// round 7
// speedup vs baseline: 3.0284x; 1.9155x over previous
#include <cuda_runtime.h>
#include <cstdint>

// ---------------------------------------------------------------------------
// NormEMAVectorQuantizer (sm_103a via compute_103) — round 7
// TF32 mma.sync screen (1 product, conflict-free LDS, cheap top-2 epilogue)
// + rigorous gap test + register-resident exact fp32 fixup on transposed codes.
//   out = concat( z_q[262144], loss[1], token_ids[8192],
//                 new_embedding[262144], new_cluster_sizes[8192] ) = 540673 f32
// ---------------------------------------------------------------------------

#define N_VEC   8192
#define N_TOK   8192
#define CDIM    32
#define KSPL    2
#define THRESH  2.0e-3f     // >= 2 * 2^-10 rigorous tf32 dot-error bound (unit vecs)

#define OFF_ZQ    0
#define OFF_LOSS  262144
#define OFF_TOK   262145
#define OFF_EMB   270337
#define OFF_CSZ   532481

// B layout: per code 40 words (32 tf32, fragment-pair reordered, +8 pad)
// stride 40 -> LDS bank = 8*g4 + 2*l4 (+8*kc): conflict-free 64-bit loads
#define EPKW        40
#define CODE_BYTES  160
#define NB_CODES    128
#define STAGE_BYTES (NB_CODES * CODE_BYTES)   // 20480
#define SMEM_TOTAL  (2 * STAGE_BYTES)         // 40960

// scratch (__device__ globals; no allocations allowed)
__device__ float              g_zn[N_VEC * CDIM];
__device__ uint32_t           g_qpk[N_VEC * CDIM];     // tf32, dense
__device__ uint32_t           g_epk[N_TOK * EPKW];     // tf32, reordered
__device__ float              g_ekT[CDIM * N_TOK];     // fp32 codes, TRANSPOSED
__device__ unsigned long long g_t1[KSPL * N_VEC];      // packed (val|inv idx)
__device__ float              g_t2v[KSPL * N_VEC];     // runner-up value
__device__ unsigned long long g_key[N_VEC];
__device__ int                g_fix[N_VEC];
__device__ int                g_nfix;
__device__ float              g_bins[N_TOK];
__device__ float              g_esum[N_TOK * CDIM];
__device__ float              g_loss;

// ---------------- helpers ---------------------------------------------------
static __device__ __forceinline__ uint32_t smem_u32(const void* p) {
    uint32_t a;
    asm("{ .reg .u64 t; cvta.to.shared.u64 t, %1; cvt.u32.u64 %0, t; }" : "=r"(a) : "l"(p));
    return a;
}
static __device__ __forceinline__ unsigned int ordered_u32(float v) {
    unsigned int b = __float_as_uint(v);
    return (b & 0x80000000u) ? ~b : (b | 0x80000000u);
}
static __device__ __forceinline__ float unordered_f32(unsigned int u) {
    unsigned int b = (u & 0x80000000u) ? (u & 0x7fffffffu) : ~u;
    return __uint_as_float(b);
}
static __device__ __forceinline__ uint32_t to_tf32(float x) {
    uint32_t r;
    asm("cvt.rna.tf32.f32 %0, %1;" : "=r"(r) : "f"(x));
    return r;
}
// reorder word c (0..31) of a code row so B-fragment pairs are adjacent:
static __device__ __forceinline__ int b_reorder(int c) {
    int kc = c >> 3, r = c & 7;
    return kc * 8 + ((r < 4) ? (r * 2) : ((r - 4) * 2 + 1));
}

#define MMA_TF32(D, Af, Bf)                                                   \
    asm volatile(                                                             \
        "mma.sync.aligned.m16n8k8.row.col.f32.tf32.tf32.f32 "                 \
        "{%0,%1,%2,%3}, {%4,%5,%6,%7}, {%8,%9}, {%0,%1,%2,%3};"               \
        : "+f"((D)[0]), "+f"((D)[1]), "+f"((D)[2]), "+f"((D)[3])              \
        : "r"((Af)[0]), "r"((Af)[1]), "r"((Af)[2]), "r"((Af)[3]),             \
          "r"((Bf)[0]), "r"((Bf)[1]))

// ---------------------------------------------------------------------------
// K1: prep — L2norm(z)+tf32 pack; embedding tf32 reorder-pack; transposed
//     fp32 codebook (smem tile transpose); zero scratch.
// ---------------------------------------------------------------------------
#define NORM_BLKS 1024
#define ESPL_BLKS 1024
#define TRNS_BLKS 32
#define ZERO_ITEMS (N_TOK * CDIM + N_TOK)
#define ZERO_BLKS ((ZERO_ITEMS + 255) / 256)

__global__ __launch_bounds__(256) void k_prep(const float* __restrict__ z,
                                              const float* __restrict__ emb) {
    __shared__ float tile[256][33];
    if (blockIdx.x < NORM_BLKS) {
        int warp = threadIdx.x >> 5;
        int lane = threadIdx.x & 31;                 // channel c
        int n    = blockIdx.x * 8 + warp;
        int b    = n >> 8, hw = n & 255;
        float v  = z[b * (CDIM * 256) + lane * 256 + hw];
        float ss = v * v;
#pragma unroll
        for (int o = 16; o > 0; o >>= 1)
            ss += __shfl_xor_sync(0xffffffffu, ss, o);
        float inv = 1.0f / fmaxf(sqrtf(ss), 1e-12f);
        float x = v * inv;
        g_zn[n * CDIM + lane]  = x;
        g_qpk[n * CDIM + lane] = to_tf32(x);
    } else if (blockIdx.x < NORM_BLKS + ESPL_BLKS) {
        int i = (blockIdx.x - NORM_BLKS) * 256 + threadIdx.x;   // 0..262143
        int r = i >> 5, c = i & 31;
        g_epk[r * EPKW + b_reorder(c)] = to_tf32(emb[i]);
    } else if (blockIdx.x < NORM_BLKS + ESPL_BLKS + TRNS_BLKS) {
        int j = blockIdx.x - (NORM_BLKS + ESPL_BLKS);
        int rbase = j * 256;
#pragma unroll 4
        for (int jj = 0; jj < 32; jj++) {
            int idx = jj * 256 + threadIdx.x;         // coalesced read
            tile[idx >> 5][idx & 31] = emb[rbase * 32 + idx];
        }
        __syncthreads();
#pragma unroll
        for (int jj = 0; jj < 4; jj++) {
            int c = jj * 8 + (threadIdx.x >> 5);
#pragma unroll
            for (int inner = 0; inner < 8; inner++) {
                int r = inner * 32 + (threadIdx.x & 31);
                g_ekT[c * N_TOK + rbase + r] = tile[r][c];   // coalesced write
            }
        }
    } else {
        int i = (blockIdx.x - NORM_BLKS - ESPL_BLKS - TRNS_BLKS) * 256 + threadIdx.x;
        if (i < N_TOK * CDIM) g_esum[i] = 0.0f;
        else if (i < ZERO_ITEMS) g_bins[i - N_TOK * CDIM] = 0.0f;
        if (i == 0) { g_loss = 0.0f; g_nfix = 0; }
    }
}

// ---------------------------------------------------------------------------
// K2: TF32 mma.sync screen + fused top-2 (fmax-tree, rare index resolve).
// grid (64, 2), 256 threads (8 warps). Warp = 16 queries; CTA = 128 queries
// x 4096 codes. B staged via cp.async double buffer.
// ---------------------------------------------------------------------------
__global__ __launch_bounds__(256) void k_mma() {
    extern __shared__ uint32_t smem[];
    uint32_t sbase = smem_u32(smem);
    int tid = threadIdx.x, wid = tid >> 5, lane = tid & 31;
    int g4 = lane >> 2, l4 = lane & 3;
    int qb    = blockIdx.x * 128 + wid * 16;
    int kbase = blockIdx.y * (N_TOK / KSPL);

    uint32_t A[4][4];
    {
        const uint32_t* q0 = g_qpk + (qb + g4) * CDIM;
        const uint32_t* q8 = g_qpk + (qb + g4 + 8) * CDIM;
#pragma unroll
        for (int kc = 0; kc < 4; kc++) {
            int w = kc * 8 + l4;
            A[kc][0] = q0[w];
            A[kc][1] = q8[w];
            A[kc][2] = q0[w + 4];
            A[kc][3] = q8[w + 4];
        }
    }

    float v1a = -3.4e38f, v2a = -3.4e38f; int k1a = 0;
    float v1b = -3.4e38f, v2b = -3.4e38f; int k1b = 0;

    {
        const char* src = (const char*)g_epk + (size_t)kbase * CODE_BYTES;
#pragma unroll
        for (int j = 0; j < 5; j++) {
            int idx = tid + j * 256;                 // 1280 x 16B = 20480 exact
            asm volatile("cp.async.ca.shared.global [%0], [%1], 16;"
                         :: "r"(sbase + idx * 16), "l"(src + idx * 16) : "memory");
        }
        asm volatile("cp.async.commit_group;" ::: "memory");
    }

    for (int nb = 0; nb < (N_TOK / KSPL) / NB_CODES; nb++) {
        asm volatile("cp.async.wait_group 0;" ::: "memory");
        __syncthreads();
        if (nb + 1 < (N_TOK / KSPL) / NB_CODES) {
            const char* src = (const char*)g_epk +
                              (size_t)(kbase + (nb + 1) * NB_CODES) * CODE_BYTES;
            uint32_t dst = sbase + ((nb + 1) & 1) * STAGE_BYTES;
#pragma unroll
            for (int j = 0; j < 5; j++) {
                int idx = tid + j * 256;
                asm volatile("cp.async.ca.shared.global [%0], [%1], 16;"
                             :: "r"(dst + idx * 16), "l"(src + idx * 16) : "memory");
            }
            asm volatile("cp.async.commit_group;" ::: "memory");
        }

        const uint32_t* buf = smem + (nb & 1) * (STAGE_BYTES / 4);

#pragma unroll 1
        for (int nt = 0; nt < NB_CODES / 8; nt += 2) {
            const uint32_t* r0 = buf + (nt * 8 + g4) * EPKW + l4 * 2;
            const uint32_t* r1 = r0 + 8 * EPKW;
            float D0[4] = {0.f, 0.f, 0.f, 0.f};
            float D1[4] = {0.f, 0.f, 0.f, 0.f};
#pragma unroll
            for (int kc = 0; kc < 4; kc++) {
                uint2 b0 = *(const uint2*)(r0 + kc * 8);
                uint2 b1 = *(const uint2*)(r1 + kc * 8);
                uint32_t B0[2] = {b0.x, b0.y};
                uint32_t B1[2] = {b1.x, b1.y};
                MMA_TF32(D0, A[kc], B0);
                MMA_TF32(D1, A[kc], B1);
            }

            int c0 = kbase + nb * NB_CODES + nt * 8 + l4 * 2;
            // row a candidates: D0[0]@c0, D0[1]@c0+1, D1[0]@c0+8, D1[1]@c0+9
            {
                float m01 = fmaxf(D0[0], D0[1]);
                float m23 = fmaxf(D1[0], D1[1]);
                float vm  = fmaxf(m01, m23);
                if (vm > v1a) {
                    int kk;
                    if (D0[0] == vm)      kk = c0;
                    else if (D0[1] == vm) kk = c0 + 1;
                    else if (D1[0] == vm) kk = c0 + 8;
                    else                  kk = c0 + 9;
                    float sec = (m01 >= m23) ? fmaxf(fminf(D0[0], D0[1]), m23)
                                             : fmaxf(m01, fminf(D1[0], D1[1]));
                    v2a = fmaxf(fmaxf(v2a, v1a), sec);
                    v1a = vm; k1a = kk;
                } else {
                    v2a = fmaxf(v2a, vm);
                }
            }
            // row b candidates: D0[2], D0[3], D1[2], D1[3]
            {
                float m01 = fmaxf(D0[2], D0[3]);
                float m23 = fmaxf(D1[2], D1[3]);
                float vm  = fmaxf(m01, m23);
                if (vm > v1b) {
                    int kk;
                    if (D0[2] == vm)      kk = c0;
                    else if (D0[3] == vm) kk = c0 + 1;
                    else if (D1[2] == vm) kk = c0 + 8;
                    else                  kk = c0 + 9;
                    float sec = (m01 >= m23) ? fmaxf(fminf(D0[2], D0[3]), m23)
                                             : fmaxf(m01, fminf(D1[2], D1[3]));
                    v2b = fmaxf(fmaxf(v2b, v1b), sec);
                    v1b = vm; k1b = kk;
                } else {
                    v2b = fmaxf(v2b, vm);
                }
            }
        }
    }

    // reduce top-2 across the 4 lanes of each row group (xor 1, 2)
#pragma unroll
    for (int d = 1; d < 4; d <<= 1) {
        float ov1; int ok1; float ov2;
        ov1 = __shfl_xor_sync(0xffffffffu, v1a, d);
        ok1 = __shfl_xor_sync(0xffffffffu, k1a, d);
        ov2 = __shfl_xor_sync(0xffffffffu, v2a, d);
        {
            bool take = (ov1 > v1a) || (ov1 == v1a && ok1 < k1a);
            float lose = take ? v1a : ov1;
            v2a = fmaxf(fmaxf(v2a, ov2), lose);
            if (take) { v1a = ov1; k1a = ok1; }
        }
        ov1 = __shfl_xor_sync(0xffffffffu, v1b, d);
        ok1 = __shfl_xor_sync(0xffffffffu, k1b, d);
        ov2 = __shfl_xor_sync(0xffffffffu, v2b, d);
        {
            bool take = (ov1 > v1b) || (ov1 == v1b && ok1 < k1b);
            float lose = take ? v1b : ov1;
            v2b = fmaxf(fmaxf(v2b, ov2), lose);
            if (take) { v1b = ov1; k1b = ok1; }
        }
    }
    if (l4 == 0) {
        int q = qb + g4;
        int sp = blockIdx.y;
        g_t1[sp * N_VEC + q] =
            ((unsigned long long)ordered_u32(v1a) << 32) |
            (unsigned int)(N_TOK - 1 - k1a);
        g_t2v[sp * N_VEC + q] = v2a;
        g_t1[sp * N_VEC + q + 8] =
            ((unsigned long long)ordered_u32(v1b) << 32) |
            (unsigned int)(N_TOK - 1 - k1b);
        g_t2v[sp * N_VEC + q + 8] = v2b;
    }
}

// ---------------------------------------------------------------------------
// K3: merge splits, gap test, build fixup list
// ---------------------------------------------------------------------------
__global__ __launch_bounds__(256) void k_merge() {
    int n = blockIdx.x * 256 + threadIdx.x;
    unsigned long long a = g_t1[n], b = g_t1[N_VEC + n];
    unsigned long long win = a > b ? a : b;
    unsigned long long lose = a > b ? b : a;
    float v2 = fmaxf(fmaxf(g_t2v[n], g_t2v[N_VEC + n]),
                     unordered_f32((unsigned int)(lose >> 32)));
    float v1 = unordered_f32((unsigned int)(win >> 32));
    if (v1 - v2 < THRESH) {
        g_key[n] = 0ull;                 // exact pass will atomicMax real keys
        int i = atomicAdd(&g_nfix, 1);
        g_fix[i] = n;
    } else {
        g_key[n] = win;
    }
}

// ---------------------------------------------------------------------------
// K4: exact fp32 rescan for flagged queries (transposed codes, reg-resident).
// grid 2048 = 64 query-group slots x 32 code chunks; block = 128 threads.
// Thread holds 2 code rows in regs; loops 32 queries from smem (32x reuse).
// ---------------------------------------------------------------------------
#define FIX_QG 64
__global__ __launch_bounds__(128) void k_fixup() {
    __shared__ int   qid[32];
    __shared__ float zq[32][32];
    __shared__ unsigned long long wbest[32][4];
    int cnt = g_nfix;
    int chunk = blockIdx.x & 31;
    int qslot = blockIdx.x >> 5;
    if (qslot * 32 >= cnt) return;
    int t = threadIdx.x, wd = t >> 5, ln = t & 31;

    int ka = chunk * 256 + t;
    int kb = ka + 128;
    float ra[CDIM], rb[CDIM];
#pragma unroll
    for (int c = 0; c < CDIM; c++) {
        ra[c] = g_ekT[c * N_TOK + ka];     // lane-consecutive: coalesced
        rb[c] = g_ekT[c * N_TOK + kb];
    }

    for (int qg = qslot; qg * 32 < cnt; qg += FIX_QG) {
        int nq = cnt - qg * 32;
        if (nq > 32) nq = 32;
        if (t < 32) qid[t] = (t < nq) ? g_fix[qg * 32 + t] : -1;
        __syncthreads();
#pragma unroll
        for (int j = 0; j < 8; j++) {
            int idx = t + j * 128;
            int q = idx >> 5, c = idx & 31;
            int n = qid[q];
            zq[q][c] = (n >= 0) ? g_zn[n * CDIM + c] : 0.0f;
        }
        __syncthreads();

        for (int q = 0; q < nq; q++) {
            float s1 = 0.0f, s2 = 0.0f;
#pragma unroll
            for (int c = 0; c < CDIM; c++) {
                float zc = zq[q][c];                 // broadcast LDS
                s1 = fmaf(zc, ra[c], s1);
                s2 = fmaf(zc, rb[c], s2);
            }
            unsigned long long key1 =
                ((unsigned long long)ordered_u32(s1) << 32) |
                (unsigned int)(N_TOK - 1 - ka);
            unsigned long long key2 =
                ((unsigned long long)ordered_u32(s2) << 32) |
                (unsigned int)(N_TOK - 1 - kb);
            unsigned long long best = key1 > key2 ? key1 : key2;
#pragma unroll
            for (int o = 16; o > 0; o >>= 1) {
                unsigned long long ov = __shfl_xor_sync(0xffffffffu, best, o);
                if (ov > best) best = ov;
            }
            if (ln == 0) wbest[q][wd] = best;
        }
        __syncthreads();
        if (t < 32 && qid[t] >= 0) {
            unsigned long long b = wbest[t][0];
#pragma unroll
            for (int w = 1; w < 4; w++) if (wbest[t][w] > b) b = wbest[t][w];
            atomicMax(&g_key[qid[t]], b);
        }
        __syncthreads();
    }
}

// ---------------------------------------------------------------------------
// K5: scatter epilogue over 262144 threads
// ---------------------------------------------------------------------------
__global__ __launch_bounds__(256) void k_scatter(const float* __restrict__ emb,
                                                 float* __restrict__ out) {
    __shared__ float red[8];
    int g  = blockIdx.x * 256 + threadIdx.x;
    int b  = g >> 13;
    int c  = (g >> 8) & 31;
    int hw = g & 255;
    int n  = b * 256 + hw;

    unsigned long long key = g_key[n];
    int bi = (N_TOK - 1) - (int)(unsigned int)(key & 0xffffffffu);

    float ev = emb[bi * CDIM + c];
    float zv = g_zn[n * CDIM + c];
    out[OFF_ZQ + g] = ev;
    if (c == 0) {
        out[OFF_TOK + n] = (float)bi;
        atomicAdd(&g_bins[bi], 1.0f);
    }
    atomicAdd(&g_esum[bi * CDIM + c], zv);

    float d = ev - zv;
    float lsum = d * d;
#pragma unroll
    for (int o = 16; o > 0; o >>= 1)
        lsum += __shfl_xor_sync(0xffffffffu, lsum, o);
    if ((threadIdx.x & 31) == 0) red[threadIdx.x >> 5] = lsum;
    __syncthreads();
    if (threadIdx.x == 0) {
        float s = 0.0f;
#pragma unroll
        for (int w = 0; w < 8; w++) s += red[w];
        atomicAdd(&g_loss, s);
    }
}

// ---------------------------------------------------------------------------
// K6: EMA codebook update + loss write
// ---------------------------------------------------------------------------
__global__ __launch_bounds__(256) void k_update(const float* __restrict__ emb,
                                                const float* __restrict__ csz,
                                                float* __restrict__ out) {
    int gtid = blockIdx.x * 256 + threadIdx.x;
    int k    = gtid >> 5;
    int lane = gtid & 31;

    float bcount = g_bins[k];
    if (lane == 0)
        out[OFF_CSZ + k] = csz[k] * 0.99f + 0.01f * bcount;

    bool  zero = (bcount == 0.0f);
    float bc   = zero ? 1.0f : bcount;
    float m    = g_esum[k * CDIM + lane] / bc;
    float ss   = m * m;
#pragma unroll
    for (int o = 16; o > 0; o >>= 1)
        ss += __shfl_xor_sync(0xffffffffu, ss, o);
    float en = m / fmaxf(sqrtf(ss), 1e-12f);

    float ev = emb[k * CDIM + lane];
    if (zero) en = ev;
    float v  = ev * 0.99f + 0.01f * en;
    float s2 = v * v;
#pragma unroll
    for (int o = 16; o > 0; o >>= 1)
        s2 += __shfl_xor_sync(0xffffffffu, s2, o);
    out[OFF_EMB + k * CDIM + lane] = v / fmaxf(sqrtf(s2), 1e-12f);

    if (gtid == 0)
        out[OFF_LOSS] = g_loss * (1.0f / (float)(N_VEC * CDIM));
}

// ---------------------------------------------------------------------------
extern "C" void kernel_launch(void* const* d_in, const int* in_sizes, int n_in,
                              void* d_out, int out_size) {
    const float* z   = (const float*)d_in[0];
    const float* emb = (const float*)d_in[1];
    const float* csz = (const float*)d_in[2];
    float* out = (float*)d_out;

    cudaFuncSetAttribute(k_mma, cudaFuncAttributeMaxDynamicSharedMemorySize, SMEM_TOTAL);

    k_prep<<<NORM_BLKS + ESPL_BLKS + TRNS_BLKS + ZERO_BLKS, 256>>>(z, emb);
    dim3 grid_mma(N_VEC / 128, KSPL);
    k_mma<<<grid_mma, 256, SMEM_TOTAL>>>();
    k_merge<<<N_VEC / 256, 256>>>();
    k_fixup<<<FIX_QG * 32, 128>>>();
    k_scatter<<<(N_VEC * CDIM) / 256, 256>>>(emb, out);
    k_update<<<(N_TOK * CDIM) / 256, 256>>>(emb, csz, out);
}

// round 8
// speedup vs baseline: 3.0868x; 1.0193x over previous
#include <cuda_runtime.h>
#include <cstdint>

// ---------------------------------------------------------------------------
// NormEMAVectorQuantizer (sm_103a via compute_103) — round 8
// TF32 mma.sync screen + rigorous gap test + high-parallelism exact fixup.
//   out = concat( z_q[262144], loss[1], token_ids[8192],
//                 new_embedding[262144], new_cluster_sizes[8192] ) = 540673 f32
// ---------------------------------------------------------------------------

#define N_VEC   8192
#define N_TOK   8192
#define CDIM    32
#define KSPL    2
#define THRESH  2.0e-3f     // >= 2 * 2^-10 rigorous tf32 dot-error bound (unit vecs)

#define OFF_ZQ    0
#define OFF_LOSS  262144
#define OFF_TOK   262145
#define OFF_EMB   270337
#define OFF_CSZ   532481

// B layout: per code 40 words (32 tf32, fragment-pair reordered, +8 pad)
#define EPKW        40
#define CODE_BYTES  160
#define NB_CODES    128
#define STAGE_BYTES (NB_CODES * CODE_BYTES)   // 20480
#define SMEM_TOTAL  (2 * STAGE_BYTES)         // 40960

// scratch (__device__ globals; no allocations allowed)
__device__ float              g_zn[N_VEC * CDIM];
__device__ uint32_t           g_qpk[N_VEC * CDIM];     // tf32, dense
__device__ uint32_t           g_epk[N_TOK * EPKW];     // tf32, reordered
__device__ float              g_ekT[CDIM * N_TOK];     // fp32 codes, TRANSPOSED
__device__ unsigned long long g_t1[KSPL * N_VEC];      // packed (val|inv idx)
__device__ float              g_t2v[KSPL * N_VEC];     // runner-up value
__device__ unsigned long long g_key[N_VEC];
__device__ int                g_fix[N_VEC];
__device__ int                g_nfix;
__device__ float              g_bins[N_TOK];
__device__ float              g_esum[N_TOK * CDIM];
__device__ float              g_loss;

// ---------------- helpers ---------------------------------------------------
static __device__ __forceinline__ uint32_t smem_u32(const void* p) {
    uint32_t a;
    asm("{ .reg .u64 t; cvta.to.shared.u64 t, %1; cvt.u32.u64 %0, t; }" : "=r"(a) : "l"(p));
    return a;
}
static __device__ __forceinline__ unsigned int ordered_u32(float v) {
    unsigned int b = __float_as_uint(v);
    return (b & 0x80000000u) ? ~b : (b | 0x80000000u);
}
static __device__ __forceinline__ float unordered_f32(unsigned int u) {
    unsigned int b = (u & 0x80000000u) ? (u & 0x7fffffffu) : ~u;
    return __uint_as_float(b);
}
static __device__ __forceinline__ uint32_t to_tf32(float x) {
    uint32_t r;
    asm("cvt.rna.tf32.f32 %0, %1;" : "=r"(r) : "f"(x));
    return r;
}
static __device__ __forceinline__ int b_reorder(int c) {
    int kc = c >> 3, r = c & 7;
    return kc * 8 + ((r < 4) ? (r * 2) : ((r - 4) * 2 + 1));
}

#define MMA_TF32(D, Af, Bf)                                                   \
    asm volatile(                                                             \
        "mma.sync.aligned.m16n8k8.row.col.f32.tf32.tf32.f32 "                 \
        "{%0,%1,%2,%3}, {%4,%5,%6,%7}, {%8,%9}, {%0,%1,%2,%3};"               \
        : "+f"((D)[0]), "+f"((D)[1]), "+f"((D)[2]), "+f"((D)[3])              \
        : "r"((Af)[0]), "r"((Af)[1]), "r"((Af)[2]), "r"((Af)[3]),             \
          "r"((Bf)[0]), "r"((Bf)[1]))

// ---------------------------------------------------------------------------
// K1: prep — L2norm(z)+tf32 pack; embedding tf32 reorder-pack; transposed
//     fp32 codebook; zero scratch.
// ---------------------------------------------------------------------------
#define NORM_BLKS 1024
#define ESPL_BLKS 1024
#define TRNS_BLKS 32
#define ZERO_ITEMS (N_TOK * CDIM + N_TOK)
#define ZERO_BLKS ((ZERO_ITEMS + 255) / 256)

__global__ __launch_bounds__(256) void k_prep(const float* __restrict__ z,
                                              const float* __restrict__ emb) {
    __shared__ float tile[256][33];
    if (blockIdx.x < NORM_BLKS) {
        int warp = threadIdx.x >> 5;
        int lane = threadIdx.x & 31;                 // channel c
        int n    = blockIdx.x * 8 + warp;
        int b    = n >> 8, hw = n & 255;
        float v  = z[b * (CDIM * 256) + lane * 256 + hw];
        float ss = v * v;
#pragma unroll
        for (int o = 16; o > 0; o >>= 1)
            ss += __shfl_xor_sync(0xffffffffu, ss, o);
        float inv = 1.0f / fmaxf(sqrtf(ss), 1e-12f);
        float x = v * inv;
        g_zn[n * CDIM + lane]  = x;
        g_qpk[n * CDIM + lane] = to_tf32(x);
    } else if (blockIdx.x < NORM_BLKS + ESPL_BLKS) {
        int i = (blockIdx.x - NORM_BLKS) * 256 + threadIdx.x;   // 0..262143
        int r = i >> 5, c = i & 31;
        g_epk[r * EPKW + b_reorder(c)] = to_tf32(emb[i]);
    } else if (blockIdx.x < NORM_BLKS + ESPL_BLKS + TRNS_BLKS) {
        int j = blockIdx.x - (NORM_BLKS + ESPL_BLKS);
        int rbase = j * 256;
#pragma unroll 4
        for (int jj = 0; jj < 32; jj++) {
            int idx = jj * 256 + threadIdx.x;         // coalesced read
            tile[idx >> 5][idx & 31] = emb[rbase * 32 + idx];
        }
        __syncthreads();
#pragma unroll
        for (int jj = 0; jj < 4; jj++) {
            int c = jj * 8 + (threadIdx.x >> 5);
#pragma unroll
            for (int inner = 0; inner < 8; inner++) {
                int r = inner * 32 + (threadIdx.x & 31);
                g_ekT[c * N_TOK + rbase + r] = tile[r][c];   // coalesced write
            }
        }
    } else {
        int i = (blockIdx.x - NORM_BLKS - ESPL_BLKS - TRNS_BLKS) * 256 + threadIdx.x;
        if (i < N_TOK * CDIM) g_esum[i] = 0.0f;
        else if (i < ZERO_ITEMS) g_bins[i - N_TOK * CDIM] = 0.0f;
        if (i == 0) { g_loss = 0.0f; g_nfix = 0; }
    }
}

// ---------------------------------------------------------------------------
// K2: TF32 mma.sync screen + fused top-2 (fmax-tree, rare index resolve).
// grid (64, 2), 256 threads (8 warps). Warp = 16 queries; CTA = 128 queries
// x 4096 codes. B staged via cp.async double buffer.
// ---------------------------------------------------------------------------
__global__ __launch_bounds__(256) void k_mma() {
    extern __shared__ uint32_t smem[];
    uint32_t sbase = smem_u32(smem);
    int tid = threadIdx.x, wid = tid >> 5, lane = tid & 31;
    int g4 = lane >> 2, l4 = lane & 3;
    int qb    = blockIdx.x * 128 + wid * 16;
    int kbase = blockIdx.y * (N_TOK / KSPL);

    uint32_t A[4][4];
    {
        const uint32_t* q0 = g_qpk + (qb + g4) * CDIM;
        const uint32_t* q8 = g_qpk + (qb + g4 + 8) * CDIM;
#pragma unroll
        for (int kc = 0; kc < 4; kc++) {
            int w = kc * 8 + l4;
            A[kc][0] = q0[w];
            A[kc][1] = q8[w];
            A[kc][2] = q0[w + 4];
            A[kc][3] = q8[w + 4];
        }
    }

    float v1a = -3.4e38f, v2a = -3.4e38f; int k1a = 0;
    float v1b = -3.4e38f, v2b = -3.4e38f; int k1b = 0;

    {
        const char* src = (const char*)g_epk + (size_t)kbase * CODE_BYTES;
#pragma unroll
        for (int j = 0; j < 5; j++) {
            int idx = tid + j * 256;
            asm volatile("cp.async.ca.shared.global [%0], [%1], 16;"
                         :: "r"(sbase + idx * 16), "l"(src + idx * 16) : "memory");
        }
        asm volatile("cp.async.commit_group;" ::: "memory");
    }

    for (int nb = 0; nb < (N_TOK / KSPL) / NB_CODES; nb++) {
        asm volatile("cp.async.wait_group 0;" ::: "memory");
        __syncthreads();
        if (nb + 1 < (N_TOK / KSPL) / NB_CODES) {
            const char* src = (const char*)g_epk +
                              (size_t)(kbase + (nb + 1) * NB_CODES) * CODE_BYTES;
            uint32_t dst = sbase + ((nb + 1) & 1) * STAGE_BYTES;
#pragma unroll
            for (int j = 0; j < 5; j++) {
                int idx = tid + j * 256;
                asm volatile("cp.async.ca.shared.global [%0], [%1], 16;"
                             :: "r"(dst + idx * 16), "l"(src + idx * 16) : "memory");
            }
            asm volatile("cp.async.commit_group;" ::: "memory");
        }

        const uint32_t* buf = smem + (nb & 1) * (STAGE_BYTES / 4);

#pragma unroll 1
        for (int nt = 0; nt < NB_CODES / 8; nt += 2) {
            const uint32_t* r0 = buf + (nt * 8 + g4) * EPKW + l4 * 2;
            const uint32_t* r1 = r0 + 8 * EPKW;
            float D0[4] = {0.f, 0.f, 0.f, 0.f};
            float D1[4] = {0.f, 0.f, 0.f, 0.f};
#pragma unroll
            for (int kc = 0; kc < 4; kc++) {
                uint2 b0 = *(const uint2*)(r0 + kc * 8);
                uint2 b1 = *(const uint2*)(r1 + kc * 8);
                uint32_t B0[2] = {b0.x, b0.y};
                uint32_t B1[2] = {b1.x, b1.y};
                MMA_TF32(D0, A[kc], B0);
                MMA_TF32(D1, A[kc], B1);
            }

            int c0 = kbase + nb * NB_CODES + nt * 8 + l4 * 2;
            {
                float m01 = fmaxf(D0[0], D0[1]);
                float m23 = fmaxf(D1[0], D1[1]);
                float vm  = fmaxf(m01, m23);
                if (vm > v1a) {
                    int kk;
                    if (D0[0] == vm)      kk = c0;
                    else if (D0[1] == vm) kk = c0 + 1;
                    else if (D1[0] == vm) kk = c0 + 8;
                    else                  kk = c0 + 9;
                    float sec = (m01 >= m23) ? fmaxf(fminf(D0[0], D0[1]), m23)
                                             : fmaxf(m01, fminf(D1[0], D1[1]));
                    v2a = fmaxf(fmaxf(v2a, v1a), sec);
                    v1a = vm; k1a = kk;
                } else {
                    v2a = fmaxf(v2a, vm);
                }
            }
            {
                float m01 = fmaxf(D0[2], D0[3]);
                float m23 = fmaxf(D1[2], D1[3]);
                float vm  = fmaxf(m01, m23);
                if (vm > v1b) {
                    int kk;
                    if (D0[2] == vm)      kk = c0;
                    else if (D0[3] == vm) kk = c0 + 1;
                    else if (D1[2] == vm) kk = c0 + 8;
                    else                  kk = c0 + 9;
                    float sec = (m01 >= m23) ? fmaxf(fminf(D0[2], D0[3]), m23)
                                             : fmaxf(m01, fminf(D1[2], D1[3]));
                    v2b = fmaxf(fmaxf(v2b, v1b), sec);
                    v1b = vm; k1b = kk;
                } else {
                    v2b = fmaxf(v2b, vm);
                }
            }
        }
    }

#pragma unroll
    for (int d = 1; d < 4; d <<= 1) {
        float ov1; int ok1; float ov2;
        ov1 = __shfl_xor_sync(0xffffffffu, v1a, d);
        ok1 = __shfl_xor_sync(0xffffffffu, k1a, d);
        ov2 = __shfl_xor_sync(0xffffffffu, v2a, d);
        {
            bool take = (ov1 > v1a) || (ov1 == v1a && ok1 < k1a);
            float lose = take ? v1a : ov1;
            v2a = fmaxf(fmaxf(v2a, ov2), lose);
            if (take) { v1a = ov1; k1a = ok1; }
        }
        ov1 = __shfl_xor_sync(0xffffffffu, v1b, d);
        ok1 = __shfl_xor_sync(0xffffffffu, k1b, d);
        ov2 = __shfl_xor_sync(0xffffffffu, v2b, d);
        {
            bool take = (ov1 > v1b) || (ov1 == v1b && ok1 < k1b);
            float lose = take ? v1b : ov1;
            v2b = fmaxf(fmaxf(v2b, ov2), lose);
            if (take) { v1b = ov1; k1b = ok1; }
        }
    }
    if (l4 == 0) {
        int q = qb + g4;
        int sp = blockIdx.y;
        g_t1[sp * N_VEC + q] =
            ((unsigned long long)ordered_u32(v1a) << 32) |
            (unsigned int)(N_TOK - 1 - k1a);
        g_t2v[sp * N_VEC + q] = v2a;
        g_t1[sp * N_VEC + q + 8] =
            ((unsigned long long)ordered_u32(v1b) << 32) |
            (unsigned int)(N_TOK - 1 - k1b);
        g_t2v[sp * N_VEC + q + 8] = v2b;
    }
}

// ---------------------------------------------------------------------------
// K3: merge splits, gap test, build fixup list
// ---------------------------------------------------------------------------
__global__ __launch_bounds__(256) void k_merge() {
    int n = blockIdx.x * 256 + threadIdx.x;
    unsigned long long a = g_t1[n], b = g_t1[N_VEC + n];
    unsigned long long win = a > b ? a : b;
    unsigned long long lose = a > b ? b : a;
    float v2 = fmaxf(fmaxf(g_t2v[n], g_t2v[N_VEC + n]),
                     unordered_f32((unsigned int)(lose >> 32)));
    float v1 = unordered_f32((unsigned int)(win >> 32));
    if (v1 - v2 < THRESH) {
        g_key[n] = 0ull;
        int i = atomicAdd(&g_nfix, 1);
        g_fix[i] = n;
    } else {
        g_key[n] = win;
    }
}

// ---------------------------------------------------------------------------
// K4: exact fp32 rescan for flagged queries.
// grid 4096 = 128 query-group slots (8 queries each) x 32 code chunks.
// Thread = 2 code rows in regs; queries processed in PAIRS -> 4 independent
// FMA chains (1.0 IPC). Early-exit blocks cost nothing.
// ---------------------------------------------------------------------------
#define FIX_SLOTS 128
__global__ __launch_bounds__(128) void k_fixup() {
    __shared__ int   qid[8];
    __shared__ float zq[8][32];
    __shared__ unsigned long long wbest[8][4];
    int cnt = g_nfix;
    int chunk = blockIdx.x & 31;
    int slot  = blockIdx.x >> 5;
    if (slot * 8 >= cnt) return;
    int t = threadIdx.x, wd = t >> 5, ln = t & 31;

    int ka = chunk * 256 + t;
    int kb = ka + 128;
    float ra[CDIM], rb[CDIM];
#pragma unroll
    for (int c = 0; c < CDIM; c++) {
        ra[c] = g_ekT[c * N_TOK + ka];     // lane-consecutive: coalesced
        rb[c] = g_ekT[c * N_TOK + kb];
    }

    for (int qg = slot * 8; qg < cnt; qg += FIX_SLOTS * 8) {
        int nq = cnt - qg;
        if (nq > 8) nq = 8;
        if (t < 8) qid[t] = (t < nq) ? g_fix[qg + t] : -1;
        __syncthreads();
#pragma unroll
        for (int j = 0; j < 2; j++) {
            int idx = t + j * 128;
            int q = idx >> 5, c = idx & 31;
            int n = qid[q];
            zq[q][c] = (n >= 0) ? g_zn[n * CDIM + c] : 0.0f;
        }
        __syncthreads();

#pragma unroll 1
        for (int q = 0; q < 8; q += 2) {
            float sa0 = 0.f, sa1 = 0.f, sb0 = 0.f, sb1 = 0.f;
#pragma unroll
            for (int c = 0; c < CDIM; c++) {
                float za = zq[q][c];
                float zb = zq[q + 1][c];
                sa0 = fmaf(za, ra[c], sa0);
                sa1 = fmaf(za, rb[c], sa1);
                sb0 = fmaf(zb, ra[c], sb0);
                sb1 = fmaf(zb, rb[c], sb1);
            }
            unsigned long long keyA, keyB, tmp;
            keyA = ((unsigned long long)ordered_u32(sa0) << 32) |
                   (unsigned int)(N_TOK - 1 - ka);
            tmp  = ((unsigned long long)ordered_u32(sa1) << 32) |
                   (unsigned int)(N_TOK - 1 - kb);
            if (tmp > keyA) keyA = tmp;
            keyB = ((unsigned long long)ordered_u32(sb0) << 32) |
                   (unsigned int)(N_TOK - 1 - ka);
            tmp  = ((unsigned long long)ordered_u32(sb1) << 32) |
                   (unsigned int)(N_TOK - 1 - kb);
            if (tmp > keyB) keyB = tmp;
#pragma unroll
            for (int o = 16; o > 0; o >>= 1) {
                unsigned long long oa = __shfl_xor_sync(0xffffffffu, keyA, o);
                unsigned long long ob = __shfl_xor_sync(0xffffffffu, keyB, o);
                if (oa > keyA) keyA = oa;
                if (ob > keyB) keyB = ob;
            }
            if (ln == 0) { wbest[q][wd] = keyA; wbest[q + 1][wd] = keyB; }
        }
        __syncthreads();
        if (t < 8 && qid[t] >= 0) {
            unsigned long long b = wbest[t][0];
#pragma unroll
            for (int w = 1; w < 4; w++) if (wbest[t][w] > b) b = wbest[t][w];
            atomicMax(&g_key[qid[t]], b);
        }
        __syncthreads();
    }
}

// ---------------------------------------------------------------------------
// K5: scatter epilogue over 262144 threads
// ---------------------------------------------------------------------------
__global__ __launch_bounds__(256) void k_scatter(const float* __restrict__ emb,
                                                 float* __restrict__ out) {
    __shared__ float red[8];
    int g  = blockIdx.x * 256 + threadIdx.x;
    int b  = g >> 13;
    int c  = (g >> 8) & 31;
    int hw = g & 255;
    int n  = b * 256 + hw;

    unsigned long long key = g_key[n];
    int bi = (N_TOK - 1) - (int)(unsigned int)(key & 0xffffffffu);

    float ev = emb[bi * CDIM + c];
    float zv = g_zn[n * CDIM + c];
    out[OFF_ZQ + g] = ev;
    if (c == 0) {
        out[OFF_TOK + n] = (float)bi;
        atomicAdd(&g_bins[bi], 1.0f);
    }
    atomicAdd(&g_esum[bi * CDIM + c], zv);

    float d = ev - zv;
    float lsum = d * d;
#pragma unroll
    for (int o = 16; o > 0; o >>= 1)
        lsum += __shfl_xor_sync(0xffffffffu, lsum, o);
    if ((threadIdx.x & 31) == 0) red[threadIdx.x >> 5] = lsum;
    __syncthreads();
    if (threadIdx.x == 0) {
        float s = 0.0f;
#pragma unroll
        for (int w = 0; w < 8; w++) s += red[w];
        atomicAdd(&g_loss, s);
    }
}

// ---------------------------------------------------------------------------
// K6: EMA codebook update + loss write
// ---------------------------------------------------------------------------
__global__ __launch_bounds__(256) void k_update(const float* __restrict__ emb,
                                                const float* __restrict__ csz,
                                                float* __restrict__ out) {
    int gtid = blockIdx.x * 256 + threadIdx.x;
    int k    = gtid >> 5;
    int lane = gtid & 31;

    float bcount = g_bins[k];
    if (lane == 0)
        out[OFF_CSZ + k] = csz[k] * 0.99f + 0.01f * bcount;

    bool  zero = (bcount == 0.0f);
    float bc   = zero ? 1.0f : bcount;
    float m    = g_esum[k * CDIM + lane] / bc;
    float ss   = m * m;
#pragma unroll
    for (int o = 16; o > 0; o >>= 1)
        ss += __shfl_xor_sync(0xffffffffu, ss, o);
    float en = m / fmaxf(sqrtf(ss), 1e-12f);

    float ev = emb[k * CDIM + lane];
    if (zero) en = ev;
    float v  = ev * 0.99f + 0.01f * en;
    float s2 = v * v;
#pragma unroll
    for (int o = 16; o > 0; o >>= 1)
        s2 += __shfl_xor_sync(0xffffffffu, s2, o);
    out[OFF_EMB + k * CDIM + lane] = v / fmaxf(sqrtf(s2), 1e-12f);

    if (gtid == 0)
        out[OFF_LOSS] = g_loss * (1.0f / (float)(N_VEC * CDIM));
}

// ---------------------------------------------------------------------------
extern "C" void kernel_launch(void* const* d_in, const int* in_sizes, int n_in,
                              void* d_out, int out_size) {
    const float* z   = (const float*)d_in[0];
    const float* emb = (const float*)d_in[1];
    const float* csz = (const float*)d_in[2];
    float* out = (float*)d_out;

    cudaFuncSetAttribute(k_mma, cudaFuncAttributeMaxDynamicSharedMemorySize, SMEM_TOTAL);

    k_prep<<<NORM_BLKS + ESPL_BLKS + TRNS_BLKS + ZERO_BLKS, 256>>>(z, emb);
    dim3 grid_mma(N_VEC / 128, KSPL);
    k_mma<<<grid_mma, 256, SMEM_TOTAL>>>();
    k_merge<<<N_VEC / 256, 256>>>();
    k_fixup<<<FIX_SLOTS * 32, 128>>>();
    k_scatter<<<(N_VEC * CDIM) / 256, 256>>>(emb, out);
    k_update<<<(N_TOK * CDIM) / 256, 256>>>(emb, csz, out);
}

// round 10
// speedup vs baseline: 3.4557x; 1.1195x over previous
#include <cuda_runtime.h>
#include <cstdint>

// ---------------------------------------------------------------------------
// NormEMAVectorQuantizer (sm_103a via compute_103) — round 9
// TF32 mma.sync screen (ILP-4 chains) + gap test + exact fp32 fixup.
// Launch order arranged so ncu (-s 5 -c 1) captures k_mma.
//   out = concat( z_q[262144], loss[1], token_ids[8192],
//                 new_embedding[262144], new_cluster_sizes[8192] ) = 540673 f32
// ---------------------------------------------------------------------------

#define N_VEC   8192
#define N_TOK   8192
#define CDIM    32
#define KSPL    2
#define THRESH  2.0e-3f     // >= 2 * 2^-10 rigorous tf32 dot-error bound (unit vecs)

#define OFF_ZQ    0
#define OFF_LOSS  262144
#define OFF_TOK   262145
#define OFF_EMB   270337
#define OFF_CSZ   532481

// B layout: per code 40 words (32 tf32, fragment-pair reordered, +8 pad)
#define EPKW        40
#define CODE_BYTES  160
#define NB_CODES    128
#define STAGE_BYTES (NB_CODES * CODE_BYTES)   // 20480
#define SMEM_TOTAL  (2 * STAGE_BYTES)         // 40960

// scratch (__device__ globals; no allocations allowed)
__device__ float              g_zn[N_VEC * CDIM];
__device__ uint32_t           g_qpk[N_VEC * CDIM];     // tf32, dense
__device__ uint32_t           g_epk[N_TOK * EPKW];     // tf32, reordered
__device__ float              g_ekT[CDIM * N_TOK];     // fp32 codes, TRANSPOSED
__device__ unsigned long long g_t1[KSPL * N_VEC];      // packed (val|inv idx)
__device__ float              g_t2v[KSPL * N_VEC];     // runner-up value
__device__ unsigned long long g_key[N_VEC];
__device__ int                g_fix[N_VEC];
__device__ int                g_nfix;
__device__ float              g_bins[N_TOK];
__device__ float              g_esum[N_TOK * CDIM];
__device__ float              g_loss;

// ---------------- helpers ---------------------------------------------------
static __device__ __forceinline__ uint32_t smem_u32(const void* p) {
    uint32_t a;
    asm("{ .reg .u64 t; cvta.to.shared.u64 t, %1; cvt.u32.u64 %0, t; }" : "=r"(a) : "l"(p));
    return a;
}
static __device__ __forceinline__ unsigned int ordered_u32(float v) {
    unsigned int b = __float_as_uint(v);
    return (b & 0x80000000u) ? ~b : (b | 0x80000000u);
}
static __device__ __forceinline__ float unordered_f32(unsigned int u) {
    unsigned int b = (u & 0x80000000u) ? (u & 0x7fffffffu) : ~u;
    return __uint_as_float(b);
}
static __device__ __forceinline__ uint32_t to_tf32(float x) {
    uint32_t r;
    asm("cvt.rna.tf32.f32 %0, %1;" : "=r"(r) : "f"(x));
    return r;
}
static __device__ __forceinline__ int b_reorder(int c) {
    int kc = c >> 3, r = c & 7;
    return kc * 8 + ((r < 4) ? (r * 2) : ((r - 4) * 2 + 1));
}

#define MMA_TF32(D, Af, Bf)                                                   \
    asm volatile(                                                             \
        "mma.sync.aligned.m16n8k8.row.col.f32.tf32.tf32.f32 "                 \
        "{%0,%1,%2,%3}, {%4,%5,%6,%7}, {%8,%9}, {%0,%1,%2,%3};"               \
        : "+f"((D)[0]), "+f"((D)[1]), "+f"((D)[2]), "+f"((D)[3])              \
        : "r"((Af)[0]), "r"((Af)[1]), "r"((Af)[2]), "r"((Af)[3]),             \
          "r"((Bf)[0]), "r"((Bf)[1]))

// ---------------------------------------------------------------------------
// K1a: L2norm(z) -> g_zn + tf32 pack (1024 blocks)
// ---------------------------------------------------------------------------
__global__ __launch_bounds__(256) void k_prep_norm(const float* __restrict__ z) {
    int warp = threadIdx.x >> 5;
    int lane = threadIdx.x & 31;                 // channel c
    int n    = blockIdx.x * 8 + warp;
    int b    = n >> 8, hw = n & 255;
    float v  = z[b * (CDIM * 256) + lane * 256 + hw];
    float ss = v * v;
#pragma unroll
    for (int o = 16; o > 0; o >>= 1)
        ss += __shfl_xor_sync(0xffffffffu, ss, o);
    float inv = 1.0f / fmaxf(sqrtf(ss), 1e-12f);
    float x = v * inv;
    g_zn[n * CDIM + lane]  = x;
    g_qpk[n * CDIM + lane] = to_tf32(x);
}

// ---------------------------------------------------------------------------
// K1b: embedding tf32 reorder-pack (1024 blocks) + fp32 transpose (32 blocks)
// ---------------------------------------------------------------------------
#define ESPL_BLKS 1024
#define TRNS_BLKS 32
__global__ __launch_bounds__(256) void k_prep_epk(const float* __restrict__ emb) {
    __shared__ float tile[256][33];
    if (blockIdx.x < ESPL_BLKS) {
        int i = blockIdx.x * 256 + threadIdx.x;   // 0..262143
        int r = i >> 5, c = i & 31;
        g_epk[r * EPKW + b_reorder(c)] = to_tf32(emb[i]);
    } else {
        int j = blockIdx.x - ESPL_BLKS;
        int rbase = j * 256;
#pragma unroll 4
        for (int jj = 0; jj < 32; jj++) {
            int idx = jj * 256 + threadIdx.x;     // coalesced read
            tile[idx >> 5][idx & 31] = emb[rbase * 32 + idx];
        }
        __syncthreads();
#pragma unroll
        for (int jj = 0; jj < 4; jj++) {
            int c = jj * 8 + (threadIdx.x >> 5);
#pragma unroll
            for (int inner = 0; inner < 8; inner++) {
                int r = inner * 32 + (threadIdx.x & 31);
                g_ekT[c * N_TOK + rbase + r] = tile[r][c];   // coalesced write
            }
        }
    }
}

// ---------------------------------------------------------------------------
// K1c: zero scratch (1056 blocks)
// ---------------------------------------------------------------------------
#define ZERO_ITEMS (N_TOK * CDIM + N_TOK)
#define ZERO_BLKS ((ZERO_ITEMS + 255) / 256)
__global__ __launch_bounds__(256) void k_prep_zero() {
    int i = blockIdx.x * 256 + threadIdx.x;
    if (i < N_TOK * CDIM) g_esum[i] = 0.0f;
    else if (i < ZERO_ITEMS) g_bins[i - N_TOK * CDIM] = 0.0f;
    if (i == 0) { g_loss = 0.0f; g_nfix = 0; }
}

// ---------------------------------------------------------------------------
// K2: TF32 mma.sync screen with 4 independent accumulator chains (ILP-4).
// grid (64, 2), 256 threads (8 warps). Warp = 16 queries; CTA = 128 queries
// x 4096 codes. Per iteration: 32 codes, 16 MMAs in 4 chains.
// ---------------------------------------------------------------------------
__global__ __launch_bounds__(256) void k_mma() {
    extern __shared__ uint32_t smem[];
    uint32_t sbase = smem_u32(smem);
    int tid = threadIdx.x, wid = tid >> 5, lane = tid & 31;
    int g4 = lane >> 2, l4 = lane & 3;
    int qb    = blockIdx.x * 128 + wid * 16;
    int kbase = blockIdx.y * (N_TOK / KSPL);

    uint32_t A[4][4];
    {
        const uint32_t* q0 = g_qpk + (qb + g4) * CDIM;
        const uint32_t* q8 = g_qpk + (qb + g4 + 8) * CDIM;
#pragma unroll
        for (int kc = 0; kc < 4; kc++) {
            int w = kc * 8 + l4;
            A[kc][0] = q0[w];
            A[kc][1] = q8[w];
            A[kc][2] = q0[w + 4];
            A[kc][3] = q8[w + 4];
        }
    }

    float v1a = -3.4e38f, v2a = -3.4e38f; int k1a = 0;
    float v1b = -3.4e38f, v2b = -3.4e38f; int k1b = 0;

    {
        const char* src = (const char*)g_epk + (size_t)kbase * CODE_BYTES;
#pragma unroll
        for (int j = 0; j < 5; j++) {
            int idx = tid + j * 256;
            asm volatile("cp.async.ca.shared.global [%0], [%1], 16;"
                         :: "r"(sbase + idx * 16), "l"(src + idx * 16) : "memory");
        }
        asm volatile("cp.async.commit_group;" ::: "memory");
    }

    for (int nb = 0; nb < (N_TOK / KSPL) / NB_CODES; nb++) {
        asm volatile("cp.async.wait_group 0;" ::: "memory");
        __syncthreads();
        if (nb + 1 < (N_TOK / KSPL) / NB_CODES) {
            const char* src = (const char*)g_epk +
                              (size_t)(kbase + (nb + 1) * NB_CODES) * CODE_BYTES;
            uint32_t dst = sbase + ((nb + 1) & 1) * STAGE_BYTES;
#pragma unroll
            for (int j = 0; j < 5; j++) {
                int idx = tid + j * 256;
                asm volatile("cp.async.ca.shared.global [%0], [%1], 16;"
                             :: "r"(dst + idx * 16), "l"(src + idx * 16) : "memory");
            }
            asm volatile("cp.async.commit_group;" ::: "memory");
        }

        const uint32_t* buf = smem + (nb & 1) * (STAGE_BYTES / 4);

#pragma unroll 1
        for (int nt = 0; nt < NB_CODES / 8; nt += 4) {
            const uint32_t* r0 = buf + (nt * 8 + g4) * EPKW + l4 * 2;
            float D0[4] = {0.f, 0.f, 0.f, 0.f};
            float D1[4] = {0.f, 0.f, 0.f, 0.f};
            float D2[4] = {0.f, 0.f, 0.f, 0.f};
            float D3[4] = {0.f, 0.f, 0.f, 0.f};
#pragma unroll
            for (int kc = 0; kc < 4; kc++) {
                uint2 b0 = *(const uint2*)(r0 + kc * 8);
                uint2 b1 = *(const uint2*)(r0 + 8  * EPKW + kc * 8);
                uint2 b2 = *(const uint2*)(r0 + 16 * EPKW + kc * 8);
                uint2 b3 = *(const uint2*)(r0 + 24 * EPKW + kc * 8);
                uint32_t B0[2] = {b0.x, b0.y};
                uint32_t B1[2] = {b1.x, b1.y};
                uint32_t B2[2] = {b2.x, b2.y};
                uint32_t B3[2] = {b3.x, b3.y};
                MMA_TF32(D0, A[kc], B0);
                MMA_TF32(D1, A[kc], B1);
                MMA_TF32(D2, A[kc], B2);
                MMA_TF32(D3, A[kc], B3);
            }

            int c0 = kbase + nb * NB_CODES + nt * 8 + l4 * 2;
            // ---- row a: candidates D0[0..1], D1[0..1], D2[0..1], D3[0..1]
            {
                float m0 = fmaxf(D0[0], D0[1]);
                float m1 = fmaxf(D1[0], D1[1]);
                float m2 = fmaxf(D2[0], D2[1]);
                float m3 = fmaxf(D3[0], D3[1]);
                float vm = fmaxf(fmaxf(m0, m1), fmaxf(m2, m3));
                if (vm > v1a) {
                    float sec; int kk;
                    if (m0 == vm) {
                        sec = fmaxf(fminf(D0[0], D0[1]), fmaxf(m1, fmaxf(m2, m3)));
                        kk = (D0[0] == vm) ? c0 : c0 + 1;
                    } else if (m1 == vm) {
                        sec = fmaxf(fminf(D1[0], D1[1]), fmaxf(m0, fmaxf(m2, m3)));
                        kk = (D1[0] == vm) ? c0 + 8 : c0 + 9;
                    } else if (m2 == vm) {
                        sec = fmaxf(fminf(D2[0], D2[1]), fmaxf(m0, fmaxf(m1, m3)));
                        kk = (D2[0] == vm) ? c0 + 16 : c0 + 17;
                    } else {
                        sec = fmaxf(fminf(D3[0], D3[1]), fmaxf(m0, fmaxf(m1, m2)));
                        kk = (D3[0] == vm) ? c0 + 24 : c0 + 25;
                    }
                    v2a = fmaxf(fmaxf(v2a, v1a), sec);
                    v1a = vm; k1a = kk;
                } else {
                    v2a = fmaxf(v2a, vm);
                }
            }
            // ---- row b: candidates D0[2..3], D1[2..3], D2[2..3], D3[2..3]
            {
                float m0 = fmaxf(D0[2], D0[3]);
                float m1 = fmaxf(D1[2], D1[3]);
                float m2 = fmaxf(D2[2], D2[3]);
                float m3 = fmaxf(D3[2], D3[3]);
                float vm = fmaxf(fmaxf(m0, m1), fmaxf(m2, m3));
                if (vm > v1b) {
                    float sec; int kk;
                    if (m0 == vm) {
                        sec = fmaxf(fminf(D0[2], D0[3]), fmaxf(m1, fmaxf(m2, m3)));
                        kk = (D0[2] == vm) ? c0 : c0 + 1;
                    } else if (m1 == vm) {
                        sec = fmaxf(fminf(D1[2], D1[3]), fmaxf(m0, fmaxf(m2, m3)));
                        kk = (D1[2] == vm) ? c0 + 8 : c0 + 9;
                    } else if (m2 == vm) {
                        sec = fmaxf(fminf(D2[2], D2[3]), fmaxf(m0, fmaxf(m1, m3)));
                        kk = (D2[2] == vm) ? c0 + 16 : c0 + 17;
                    } else {
                        sec = fmaxf(fminf(D3[2], D3[3]), fmaxf(m0, fmaxf(m1, m2)));
                        kk = (D3[2] == vm) ? c0 + 24 : c0 + 25;
                    }
                    v2b = fmaxf(fmaxf(v2b, v1b), sec);
                    v1b = vm; k1b = kk;
                } else {
                    v2b = fmaxf(v2b, vm);
                }
            }
        }
    }

#pragma unroll
    for (int d = 1; d < 4; d <<= 1) {
        float ov1; int ok1; float ov2;
        ov1 = __shfl_xor_sync(0xffffffffu, v1a, d);
        ok1 = __shfl_xor_sync(0xffffffffu, k1a, d);
        ov2 = __shfl_xor_sync(0xffffffffu, v2a, d);
        {
            bool take = (ov1 > v1a) || (ov1 == v1a && ok1 < k1a);
            float lose = take ? v1a : ov1;
            v2a = fmaxf(fmaxf(v2a, ov2), lose);
            if (take) { v1a = ov1; k1a = ok1; }
        }
        ov1 = __shfl_xor_sync(0xffffffffu, v1b, d);
        ok1 = __shfl_xor_sync(0xffffffffu, k1b, d);
        ov2 = __shfl_xor_sync(0xffffffffu, v2b, d);
        {
            bool take = (ov1 > v1b) || (ov1 == v1b && ok1 < k1b);
            float lose = take ? v1b : ov1;
            v2b = fmaxf(fmaxf(v2b, ov2), lose);
            if (take) { v1b = ov1; k1b = ok1; }
        }
    }
    if (l4 == 0) {
        int q = qb + g4;
        int sp = blockIdx.y;
        g_t1[sp * N_VEC + q] =
            ((unsigned long long)ordered_u32(v1a) << 32) |
            (unsigned int)(N_TOK - 1 - k1a);
        g_t2v[sp * N_VEC + q] = v2a;
        g_t1[sp * N_VEC + q + 8] =
            ((unsigned long long)ordered_u32(v1b) << 32) |
            (unsigned int)(N_TOK - 1 - k1b);
        g_t2v[sp * N_VEC + q + 8] = v2b;
    }
}

// ---------------------------------------------------------------------------
// K3: merge splits, gap test, build fixup list
// ---------------------------------------------------------------------------
__global__ __launch_bounds__(256) void k_merge() {
    int n = blockIdx.x * 256 + threadIdx.x;
    unsigned long long a = g_t1[n], b = g_t1[N_VEC + n];
    unsigned long long win = a > b ? a : b;
    unsigned long long lose = a > b ? b : a;
    float v2 = fmaxf(fmaxf(g_t2v[n], g_t2v[N_VEC + n]),
                     unordered_f32((unsigned int)(lose >> 32)));
    float v1 = unordered_f32((unsigned int)(win >> 32));
    if (v1 - v2 < THRESH) {
        g_key[n] = 0ull;
        int i = atomicAdd(&g_nfix, 1);
        g_fix[i] = n;
    } else {
        g_key[n] = win;
    }
}

// ---------------------------------------------------------------------------
// K4: exact fp32 rescan for flagged queries (pairs -> 4 FMA chains).
// ---------------------------------------------------------------------------
#define FIX_SLOTS 128
__global__ __launch_bounds__(128) void k_fixup() {
    __shared__ int   qid[8];
    __shared__ float zq[8][32];
    __shared__ unsigned long long wbest[8][4];
    int cnt = g_nfix;
    int chunk = blockIdx.x & 31;
    int slot  = blockIdx.x >> 5;
    if (slot * 8 >= cnt) return;
    int t = threadIdx.x, wd = t >> 5, ln = t & 31;

    int ka = chunk * 256 + t;
    int kb = ka + 128;
    float ra[CDIM], rb[CDIM];
#pragma unroll
    for (int c = 0; c < CDIM; c++) {
        ra[c] = g_ekT[c * N_TOK + ka];
        rb[c] = g_ekT[c * N_TOK + kb];
    }

    for (int qg = slot * 8; qg < cnt; qg += FIX_SLOTS * 8) {
        int nq = cnt - qg;
        if (nq > 8) nq = 8;
        if (t < 8) qid[t] = (t < nq) ? g_fix[qg + t] : -1;
        __syncthreads();
#pragma unroll
        for (int j = 0; j < 2; j++) {
            int idx = t + j * 128;
            int q = idx >> 5, c = idx & 31;
            int n = qid[q];
            zq[q][c] = (n >= 0) ? g_zn[n * CDIM + c] : 0.0f;
        }
        __syncthreads();

#pragma unroll 1
        for (int q = 0; q < 8; q += 2) {
            float sa0 = 0.f, sa1 = 0.f, sb0 = 0.f, sb1 = 0.f;
#pragma unroll
            for (int c = 0; c < CDIM; c++) {
                float za = zq[q][c];
                float zb = zq[q + 1][c];
                sa0 = fmaf(za, ra[c], sa0);
                sa1 = fmaf(za, rb[c], sa1);
                sb0 = fmaf(zb, ra[c], sb0);
                sb1 = fmaf(zb, rb[c], sb1);
            }
            unsigned long long keyA, keyB, tmp;
            keyA = ((unsigned long long)ordered_u32(sa0) << 32) |
                   (unsigned int)(N_TOK - 1 - ka);
            tmp  = ((unsigned long long)ordered_u32(sa1) << 32) |
                   (unsigned int)(N_TOK - 1 - kb);
            if (tmp > keyA) keyA = tmp;
            keyB = ((unsigned long long)ordered_u32(sb0) << 32) |
                   (unsigned int)(N_TOK - 1 - ka);
            tmp  = ((unsigned long long)ordered_u32(sb1) << 32) |
                   (unsigned int)(N_TOK - 1 - kb);
            if (tmp > keyB) keyB = tmp;
#pragma unroll
            for (int o = 16; o > 0; o >>= 1) {
                unsigned long long oa = __shfl_xor_sync(0xffffffffu, keyA, o);
                unsigned long long ob = __shfl_xor_sync(0xffffffffu, keyB, o);
                if (oa > keyA) keyA = oa;
                if (ob > keyB) keyB = ob;
            }
            if (ln == 0) { wbest[q][wd] = keyA; wbest[q + 1][wd] = keyB; }
        }
        __syncthreads();
        if (t < 8 && qid[t] >= 0) {
            unsigned long long b = wbest[t][0];
#pragma unroll
            for (int w = 1; w < 4; w++) if (wbest[t][w] > b) b = wbest[t][w];
            atomicMax(&g_key[qid[t]], b);
        }
        __syncthreads();
    }
}

// ---------------------------------------------------------------------------
// K5: scatter epilogue over 262144 threads
// ---------------------------------------------------------------------------
__global__ __launch_bounds__(256) void k_scatter(const float* __restrict__ emb,
                                                 float* __restrict__ out) {
    __shared__ float red[8];
    int g  = blockIdx.x * 256 + threadIdx.x;
    int b  = g >> 13;
    int c  = (g >> 8) & 31;
    int hw = g & 255;
    int n  = b * 256 + hw;

    unsigned long long key = g_key[n];
    int bi = (N_TOK - 1) - (int)(unsigned int)(key & 0xffffffffu);

    float ev = emb[bi * CDIM + c];
    float zv = g_zn[n * CDIM + c];
    out[OFF_ZQ + g] = ev;
    if (c == 0) {
        out[OFF_TOK + n] = (float)bi;
        atomicAdd(&g_bins[bi], 1.0f);
    }
    atomicAdd(&g_esum[bi * CDIM + c], zv);

    float d = ev - zv;
    float lsum = d * d;
#pragma unroll
    for (int o = 16; o > 0; o >>= 1)
        lsum += __shfl_xor_sync(0xffffffffu, lsum, o);
    if ((threadIdx.x & 31) == 0) red[threadIdx.x >> 5] = lsum;
    __syncthreads();
    if (threadIdx.x == 0) {
        float s = 0.0f;
#pragma unroll
        for (int w = 0; w < 8; w++) s += red[w];
        atomicAdd(&g_loss, s);
    }
}

// ---------------------------------------------------------------------------
// K6: EMA codebook update + loss write
// ---------------------------------------------------------------------------
__global__ __launch_bounds__(256) void k_update(const float* __restrict__ emb,
                                                const float* __restrict__ csz,
                                                float* __restrict__ out) {
    int gtid = blockIdx.x * 256 + threadIdx.x;
    int k    = gtid >> 5;
    int lane = gtid & 31;

    float bcount = g_bins[k];
    if (lane == 0)
        out[OFF_CSZ + k] = csz[k] * 0.99f + 0.01f * bcount;

    bool  zero = (bcount == 0.0f);
    float bc   = zero ? 1.0f : bcount;
    float m    = g_esum[k * CDIM + lane] / bc;
    float ss   = m * m;
#pragma unroll
    for (int o = 16; o > 0; o >>= 1)
        ss += __shfl_xor_sync(0xffffffffu, ss, o);
    float en = m / fmaxf(sqrtf(ss), 1e-12f);

    float ev = emb[k * CDIM + lane];
    if (zero) en = ev;
    float v  = ev * 0.99f + 0.01f * en;
    float s2 = v * v;
#pragma unroll
    for (int o = 16; o > 0; o >>= 1)
        s2 += __shfl_xor_sync(0xffffffffu, s2, o);
    out[OFF_EMB + k * CDIM + lane] = v / fmaxf(sqrtf(s2), 1e-12f);

    if (gtid == 0)
        out[OFF_LOSS] = g_loss * (1.0f / (float)(N_VEC * CDIM));
}

// ---------------------------------------------------------------------------
extern "C" void kernel_launch(void* const* d_in, const int* in_sizes, int n_in,
                              void* d_out, int out_size) {
    const float* z   = (const float*)d_in[0];
    const float* emb = (const float*)d_in[1];
    const float* csz = (const float*)d_in[2];
    float* out = (float*)d_out;

    cudaFuncSetAttribute(k_mma, cudaFuncAttributeMaxDynamicSharedMemorySize, SMEM_TOTAL);

    k_prep_norm<<<N_VEC / 8, 256>>>(z);                      // launch 0
    k_prep_epk<<<ESPL_BLKS + TRNS_BLKS, 256>>>(emb);         // launch 1
    k_prep_zero<<<ZERO_BLKS, 256>>>();                       // launch 2
    dim3 grid_mma(N_VEC / 128, KSPL);
    k_mma<<<grid_mma, 256, SMEM_TOTAL>>>();                  // launch 3  <- ncu
    k_merge<<<N_VEC / 256, 256>>>();                         // launch 4
    k_fixup<<<FIX_SLOTS * 32, 128>>>();                      // launch 5
    k_scatter<<<(N_VEC * CDIM) / 256, 256>>>(emb, out);      // launch 6
    k_update<<<(N_TOK * CDIM) / 256, 256>>>(emb, csz, out);  // launch 7
}

// round 11
// speedup vs baseline: 3.9734x; 1.1498x over previous
#include <cuda_runtime.h>
#include <cstdint>

// ---------------------------------------------------------------------------
// NormEMAVectorQuantizer (sm_103a via compute_103) — round 11
// TF32 mma.sync screen (ILP-4, KSPL=4 for 2 CTAs/SM) + gap test + exact fixup.
//   out = concat( z_q[262144], loss[1], token_ids[8192],
//                 new_embedding[262144], new_cluster_sizes[8192] ) = 540673 f32
// ---------------------------------------------------------------------------

#define N_VEC   8192
#define N_TOK   8192
#define CDIM    32
#define KSPL    4
#define THRESH  2.0e-3f     // >= 2 * 2^-10 rigorous tf32 dot-error bound (unit vecs)

#define OFF_ZQ    0
#define OFF_LOSS  262144
#define OFF_TOK   262145
#define OFF_EMB   270337
#define OFF_CSZ   532481

// B layout: per code 40 words (32 tf32, fragment-pair reordered, +8 pad)
#define EPKW        40
#define CODE_BYTES  160
#define NB_CODES    128
#define STAGE_BYTES (NB_CODES * CODE_BYTES)   // 20480
#define SMEM_TOTAL  (2 * STAGE_BYTES)         // 40960

// scratch (__device__ globals; no allocations allowed)
__device__ float              g_zn[N_VEC * CDIM];
__device__ uint32_t           g_qpk[N_VEC * CDIM];     // tf32, dense
__device__ uint32_t           g_epk[N_TOK * EPKW];     // tf32, reordered
__device__ float              g_ekT[CDIM * N_TOK];     // fp32 codes, TRANSPOSED
__device__ unsigned long long g_t1[KSPL * N_VEC];      // packed (val|inv idx)
__device__ float              g_t2v[KSPL * N_VEC];     // runner-up value
__device__ unsigned long long g_key[N_VEC];
__device__ int                g_fix[N_VEC];
__device__ int                g_nfix;
__device__ float              g_bins[N_TOK];
__device__ float              g_esum[N_TOK * CDIM];
__device__ float              g_loss;

// ---------------- helpers ---------------------------------------------------
static __device__ __forceinline__ uint32_t smem_u32(const void* p) {
    uint32_t a;
    asm("{ .reg .u64 t; cvta.to.shared.u64 t, %1; cvt.u32.u64 %0, t; }" : "=r"(a) : "l"(p));
    return a;
}
static __device__ __forceinline__ unsigned int ordered_u32(float v) {
    unsigned int b = __float_as_uint(v);
    return (b & 0x80000000u) ? ~b : (b | 0x80000000u);
}
static __device__ __forceinline__ float unordered_f32(unsigned int u) {
    unsigned int b = (u & 0x80000000u) ? (u & 0x7fffffffu) : ~u;
    return __uint_as_float(b);
}
static __device__ __forceinline__ uint32_t to_tf32(float x) {
    uint32_t r;
    asm("cvt.rna.tf32.f32 %0, %1;" : "=r"(r) : "f"(x));
    return r;
}
static __device__ __forceinline__ int b_reorder(int c) {
    int kc = c >> 3, r = c & 7;
    return kc * 8 + ((r < 4) ? (r * 2) : ((r - 4) * 2 + 1));
}

#define MMA_TF32(D, Af, Bf)                                                   \
    asm volatile(                                                             \
        "mma.sync.aligned.m16n8k8.row.col.f32.tf32.tf32.f32 "                 \
        "{%0,%1,%2,%3}, {%4,%5,%6,%7}, {%8,%9}, {%0,%1,%2,%3};"               \
        : "+f"((D)[0]), "+f"((D)[1]), "+f"((D)[2]), "+f"((D)[3])              \
        : "r"((Af)[0]), "r"((Af)[1]), "r"((Af)[2]), "r"((Af)[3]),             \
          "r"((Bf)[0]), "r"((Bf)[1]))

// ---------------------------------------------------------------------------
// K1a: L2norm(z) -> g_zn + tf32 pack (1024 blocks)
// ---------------------------------------------------------------------------
__global__ __launch_bounds__(256) void k_prep_norm(const float* __restrict__ z) {
    int warp = threadIdx.x >> 5;
    int lane = threadIdx.x & 31;                 // channel c
    int n    = blockIdx.x * 8 + warp;
    int b    = n >> 8, hw = n & 255;
    float v  = z[b * (CDIM * 256) + lane * 256 + hw];
    float ss = v * v;
#pragma unroll
    for (int o = 16; o > 0; o >>= 1)
        ss += __shfl_xor_sync(0xffffffffu, ss, o);
    float inv = 1.0f / fmaxf(sqrtf(ss), 1e-12f);
    float x = v * inv;
    g_zn[n * CDIM + lane]  = x;
    g_qpk[n * CDIM + lane] = to_tf32(x);
}

// ---------------------------------------------------------------------------
// K1b: embedding tf32 reorder-pack (1024 blocks) + fp32 transpose (32 blocks)
// ---------------------------------------------------------------------------
#define ESPL_BLKS 1024
#define TRNS_BLKS 32
__global__ __launch_bounds__(256) void k_prep_epk(const float* __restrict__ emb) {
    __shared__ float tile[256][33];
    if (blockIdx.x < ESPL_BLKS) {
        int i = blockIdx.x * 256 + threadIdx.x;   // 0..262143
        int r = i >> 5, c = i & 31;
        g_epk[r * EPKW + b_reorder(c)] = to_tf32(emb[i]);
    } else {
        int j = blockIdx.x - ESPL_BLKS;
        int rbase = j * 256;
#pragma unroll 4
        for (int jj = 0; jj < 32; jj++) {
            int idx = jj * 256 + threadIdx.x;     // coalesced read
            tile[idx >> 5][idx & 31] = emb[rbase * 32 + idx];
        }
        __syncthreads();
#pragma unroll
        for (int jj = 0; jj < 4; jj++) {
            int c = jj * 8 + (threadIdx.x >> 5);
#pragma unroll
            for (int inner = 0; inner < 8; inner++) {
                int r = inner * 32 + (threadIdx.x & 31);
                g_ekT[c * N_TOK + rbase + r] = tile[r][c];   // coalesced write
            }
        }
    }
}

// ---------------------------------------------------------------------------
// K1c: zero scratch
// ---------------------------------------------------------------------------
#define ZERO_ITEMS (N_TOK * CDIM + N_TOK)
#define ZERO_BLKS ((ZERO_ITEMS + 255) / 256)
__global__ __launch_bounds__(256) void k_prep_zero() {
    int i = blockIdx.x * 256 + threadIdx.x;
    if (i < N_TOK * CDIM) g_esum[i] = 0.0f;
    else if (i < ZERO_ITEMS) g_bins[i - N_TOK * CDIM] = 0.0f;
    if (i == 0) { g_loss = 0.0f; g_nfix = 0; }
}

// ---------------------------------------------------------------------------
// K2: TF32 mma.sync screen, ILP-4 chains, grid (64, 4) = 256 CTAs
// (2 CTAs/SM -> 16 warps/SM). Warp = 16 queries; CTA = 128 queries x 2048
// codes (16 stage iterations of 128 codes).
// ---------------------------------------------------------------------------
__global__ __launch_bounds__(256) void k_mma() {
    extern __shared__ uint32_t smem[];
    uint32_t sbase = smem_u32(smem);
    int tid = threadIdx.x, wid = tid >> 5, lane = tid & 31;
    int g4 = lane >> 2, l4 = lane & 3;
    int qb    = blockIdx.x * 128 + wid * 16;
    int kbase = blockIdx.y * (N_TOK / KSPL);

    uint32_t A[4][4];
    {
        const uint32_t* q0 = g_qpk + (qb + g4) * CDIM;
        const uint32_t* q8 = g_qpk + (qb + g4 + 8) * CDIM;
#pragma unroll
        for (int kc = 0; kc < 4; kc++) {
            int w = kc * 8 + l4;
            A[kc][0] = q0[w];
            A[kc][1] = q8[w];
            A[kc][2] = q0[w + 4];
            A[kc][3] = q8[w + 4];
        }
    }

    float v1a = -3.4e38f, v2a = -3.4e38f; int k1a = 0;
    float v1b = -3.4e38f, v2b = -3.4e38f; int k1b = 0;

    {
        const char* src = (const char*)g_epk + (size_t)kbase * CODE_BYTES;
#pragma unroll
        for (int j = 0; j < 5; j++) {
            int idx = tid + j * 256;
            asm volatile("cp.async.ca.shared.global [%0], [%1], 16;"
                         :: "r"(sbase + idx * 16), "l"(src + idx * 16) : "memory");
        }
        asm volatile("cp.async.commit_group;" ::: "memory");
    }

    for (int nb = 0; nb < (N_TOK / KSPL) / NB_CODES; nb++) {
        asm volatile("cp.async.wait_group 0;" ::: "memory");
        __syncthreads();
        if (nb + 1 < (N_TOK / KSPL) / NB_CODES) {
            const char* src = (const char*)g_epk +
                              (size_t)(kbase + (nb + 1) * NB_CODES) * CODE_BYTES;
            uint32_t dst = sbase + ((nb + 1) & 1) * STAGE_BYTES;
#pragma unroll
            for (int j = 0; j < 5; j++) {
                int idx = tid + j * 256;
                asm volatile("cp.async.ca.shared.global [%0], [%1], 16;"
                             :: "r"(dst + idx * 16), "l"(src + idx * 16) : "memory");
            }
            asm volatile("cp.async.commit_group;" ::: "memory");
        }

        const uint32_t* buf = smem + (nb & 1) * (STAGE_BYTES / 4);

#pragma unroll 1
        for (int nt = 0; nt < NB_CODES / 8; nt += 4) {
            const uint32_t* r0 = buf + (nt * 8 + g4) * EPKW + l4 * 2;
            float D0[4] = {0.f, 0.f, 0.f, 0.f};
            float D1[4] = {0.f, 0.f, 0.f, 0.f};
            float D2[4] = {0.f, 0.f, 0.f, 0.f};
            float D3[4] = {0.f, 0.f, 0.f, 0.f};
#pragma unroll
            for (int kc = 0; kc < 4; kc++) {
                uint2 b0 = *(const uint2*)(r0 + kc * 8);
                uint2 b1 = *(const uint2*)(r0 + 8  * EPKW + kc * 8);
                uint2 b2 = *(const uint2*)(r0 + 16 * EPKW + kc * 8);
                uint2 b3 = *(const uint2*)(r0 + 24 * EPKW + kc * 8);
                uint32_t B0[2] = {b0.x, b0.y};
                uint32_t B1[2] = {b1.x, b1.y};
                uint32_t B2[2] = {b2.x, b2.y};
                uint32_t B3[2] = {b3.x, b3.y};
                MMA_TF32(D0, A[kc], B0);
                MMA_TF32(D1, A[kc], B1);
                MMA_TF32(D2, A[kc], B2);
                MMA_TF32(D3, A[kc], B3);
            }

            int c0 = kbase + nb * NB_CODES + nt * 8 + l4 * 2;
            {
                float m0 = fmaxf(D0[0], D0[1]);
                float m1 = fmaxf(D1[0], D1[1]);
                float m2 = fmaxf(D2[0], D2[1]);
                float m3 = fmaxf(D3[0], D3[1]);
                float vm = fmaxf(fmaxf(m0, m1), fmaxf(m2, m3));
                if (vm > v1a) {
                    float sec; int kk;
                    if (m0 == vm) {
                        sec = fmaxf(fminf(D0[0], D0[1]), fmaxf(m1, fmaxf(m2, m3)));
                        kk = (D0[0] == vm) ? c0 : c0 + 1;
                    } else if (m1 == vm) {
                        sec = fmaxf(fminf(D1[0], D1[1]), fmaxf(m0, fmaxf(m2, m3)));
                        kk = (D1[0] == vm) ? c0 + 8 : c0 + 9;
                    } else if (m2 == vm) {
                        sec = fmaxf(fminf(D2[0], D2[1]), fmaxf(m0, fmaxf(m1, m3)));
                        kk = (D2[0] == vm) ? c0 + 16 : c0 + 17;
                    } else {
                        sec = fmaxf(fminf(D3[0], D3[1]), fmaxf(m0, fmaxf(m1, m2)));
                        kk = (D3[0] == vm) ? c0 + 24 : c0 + 25;
                    }
                    v2a = fmaxf(fmaxf(v2a, v1a), sec);
                    v1a = vm; k1a = kk;
                } else {
                    v2a = fmaxf(v2a, vm);
                }
            }
            {
                float m0 = fmaxf(D0[2], D0[3]);
                float m1 = fmaxf(D1[2], D1[3]);
                float m2 = fmaxf(D2[2], D2[3]);
                float m3 = fmaxf(D3[2], D3[3]);
                float vm = fmaxf(fmaxf(m0, m1), fmaxf(m2, m3));
                if (vm > v1b) {
                    float sec; int kk;
                    if (m0 == vm) {
                        sec = fmaxf(fminf(D0[2], D0[3]), fmaxf(m1, fmaxf(m2, m3)));
                        kk = (D0[2] == vm) ? c0 : c0 + 1;
                    } else if (m1 == vm) {
                        sec = fmaxf(fminf(D1[2], D1[3]), fmaxf(m0, fmaxf(m2, m3)));
                        kk = (D1[2] == vm) ? c0 + 8 : c0 + 9;
                    } else if (m2 == vm) {
                        sec = fmaxf(fminf(D2[2], D2[3]), fmaxf(m0, fmaxf(m1, m3)));
                        kk = (D2[2] == vm) ? c0 + 16 : c0 + 17;
                    } else {
                        sec = fmaxf(fminf(D3[2], D3[3]), fmaxf(m0, fmaxf(m1, m2)));
                        kk = (D3[2] == vm) ? c0 + 24 : c0 + 25;
                    }
                    v2b = fmaxf(fmaxf(v2b, v1b), sec);
                    v1b = vm; k1b = kk;
                } else {
                    v2b = fmaxf(v2b, vm);
                }
            }
        }
    }

#pragma unroll
    for (int d = 1; d < 4; d <<= 1) {
        float ov1; int ok1; float ov2;
        ov1 = __shfl_xor_sync(0xffffffffu, v1a, d);
        ok1 = __shfl_xor_sync(0xffffffffu, k1a, d);
        ov2 = __shfl_xor_sync(0xffffffffu, v2a, d);
        {
            bool take = (ov1 > v1a) || (ov1 == v1a && ok1 < k1a);
            float lose = take ? v1a : ov1;
            v2a = fmaxf(fmaxf(v2a, ov2), lose);
            if (take) { v1a = ov1; k1a = ok1; }
        }
        ov1 = __shfl_xor_sync(0xffffffffu, v1b, d);
        ok1 = __shfl_xor_sync(0xffffffffu, k1b, d);
        ov2 = __shfl_xor_sync(0xffffffffu, v2b, d);
        {
            bool take = (ov1 > v1b) || (ov1 == v1b && ok1 < k1b);
            float lose = take ? v1b : ov1;
            v2b = fmaxf(fmaxf(v2b, ov2), lose);
            if (take) { v1b = ov1; k1b = ok1; }
        }
    }
    if (l4 == 0) {
        int q = qb + g4;
        int sp = blockIdx.y;
        g_t1[sp * N_VEC + q] =
            ((unsigned long long)ordered_u32(v1a) << 32) |
            (unsigned int)(N_TOK - 1 - k1a);
        g_t2v[sp * N_VEC + q] = v2a;
        g_t1[sp * N_VEC + q + 8] =
            ((unsigned long long)ordered_u32(v1b) << 32) |
            (unsigned int)(N_TOK - 1 - k1b);
        g_t2v[sp * N_VEC + q + 8] = v2b;
    }
}

// ---------------------------------------------------------------------------
// K3: merge KSPL splits' top-2, gap test, build fixup list
// ---------------------------------------------------------------------------
__global__ __launch_bounds__(256) void k_merge() {
    int n = blockIdx.x * 256 + threadIdx.x;
    unsigned long long win = 0ull;
    float v2 = -3.4e38f;
#pragma unroll
    for (int s = 0; s < KSPL; s++) {
        unsigned long long t = g_t1[s * N_VEC + n];
        float tv2 = g_t2v[s * N_VEC + n];
        if (t > win) {
            v2 = fmaxf(v2, unordered_f32((unsigned int)(win >> 32)));
            win = t;
        } else {
            v2 = fmaxf(v2, unordered_f32((unsigned int)(t >> 32)));
        }
        v2 = fmaxf(v2, tv2);
    }
    float v1 = unordered_f32((unsigned int)(win >> 32));
    if (v1 - v2 < THRESH) {
        g_key[n] = 0ull;
        int i = atomicAdd(&g_nfix, 1);
        g_fix[i] = n;
    } else {
        g_key[n] = win;
    }
}

// ---------------------------------------------------------------------------
// K4: exact fp32 rescan for flagged queries (pairs -> 4 FMA chains).
// ---------------------------------------------------------------------------
#define FIX_SLOTS 128
__global__ __launch_bounds__(128) void k_fixup() {
    __shared__ int   qid[8];
    __shared__ float zq[8][32];
    __shared__ unsigned long long wbest[8][4];
    int cnt = g_nfix;
    int chunk = blockIdx.x & 31;
    int slot  = blockIdx.x >> 5;
    if (slot * 8 >= cnt) return;
    int t = threadIdx.x, wd = t >> 5, ln = t & 31;

    int ka = chunk * 256 + t;
    int kb = ka + 128;
    float ra[CDIM], rb[CDIM];
#pragma unroll
    for (int c = 0; c < CDIM; c++) {
        ra[c] = g_ekT[c * N_TOK + ka];
        rb[c] = g_ekT[c * N_TOK + kb];
    }

    for (int qg = slot * 8; qg < cnt; qg += FIX_SLOTS * 8) {
        int nq = cnt - qg;
        if (nq > 8) nq = 8;
        if (t < 8) qid[t] = (t < nq) ? g_fix[qg + t] : -1;
        __syncthreads();
#pragma unroll
        for (int j = 0; j < 2; j++) {
            int idx = t + j * 128;
            int q = idx >> 5, c = idx & 31;
            int n = qid[q];
            zq[q][c] = (n >= 0) ? g_zn[n * CDIM + c] : 0.0f;
        }
        __syncthreads();

#pragma unroll 1
        for (int q = 0; q < 8; q += 2) {
            float sa0 = 0.f, sa1 = 0.f, sb0 = 0.f, sb1 = 0.f;
#pragma unroll
            for (int c = 0; c < CDIM; c++) {
                float za = zq[q][c];
                float zb = zq[q + 1][c];
                sa0 = fmaf(za, ra[c], sa0);
                sa1 = fmaf(za, rb[c], sa1);
                sb0 = fmaf(zb, ra[c], sb0);
                sb1 = fmaf(zb, rb[c], sb1);
            }
            unsigned long long keyA, keyB, tmp;
            keyA = ((unsigned long long)ordered_u32(sa0) << 32) |
                   (unsigned int)(N_TOK - 1 - ka);
            tmp  = ((unsigned long long)ordered_u32(sa1) << 32) |
                   (unsigned int)(N_TOK - 1 - kb);
            if (tmp > keyA) keyA = tmp;
            keyB = ((unsigned long long)ordered_u32(sb0) << 32) |
                   (unsigned int)(N_TOK - 1 - ka);
            tmp  = ((unsigned long long)ordered_u32(sb1) << 32) |
                   (unsigned int)(N_TOK - 1 - kb);
            if (tmp > keyB) keyB = tmp;
#pragma unroll
            for (int o = 16; o > 0; o >>= 1) {
                unsigned long long oa = __shfl_xor_sync(0xffffffffu, keyA, o);
                unsigned long long ob = __shfl_xor_sync(0xffffffffu, keyB, o);
                if (oa > keyA) keyA = oa;
                if (ob > keyB) keyB = ob;
            }
            if (ln == 0) { wbest[q][wd] = keyA; wbest[q + 1][wd] = keyB; }
        }
        __syncthreads();
        if (t < 8 && qid[t] >= 0) {
            unsigned long long b = wbest[t][0];
#pragma unroll
            for (int w = 1; w < 4; w++) if (wbest[t][w] > b) b = wbest[t][w];
            atomicMax(&g_key[qid[t]], b);
        }
        __syncthreads();
    }
}

// ---------------------------------------------------------------------------
// K5: scatter epilogue over 262144 threads
// ---------------------------------------------------------------------------
__global__ __launch_bounds__(256) void k_scatter(const float* __restrict__ emb,
                                                 float* __restrict__ out) {
    __shared__ float red[8];
    int g  = blockIdx.x * 256 + threadIdx.x;
    int b  = g >> 13;
    int c  = (g >> 8) & 31;
    int hw = g & 255;
    int n  = b * 256 + hw;

    unsigned long long key = g_key[n];
    int bi = (N_TOK - 1) - (int)(unsigned int)(key & 0xffffffffu);

    float ev = emb[bi * CDIM + c];
    float zv = g_zn[n * CDIM + c];
    out[OFF_ZQ + g] = ev;
    if (c == 0) {
        out[OFF_TOK + n] = (float)bi;
        atomicAdd(&g_bins[bi], 1.0f);
    }
    atomicAdd(&g_esum[bi * CDIM + c], zv);

    float d = ev - zv;
    float lsum = d * d;
#pragma unroll
    for (int o = 16; o > 0; o >>= 1)
        lsum += __shfl_xor_sync(0xffffffffu, lsum, o);
    if ((threadIdx.x & 31) == 0) red[threadIdx.x >> 5] = lsum;
    __syncthreads();
    if (threadIdx.x == 0) {
        float s = 0.0f;
#pragma unroll
        for (int w = 0; w < 8; w++) s += red[w];
        atomicAdd(&g_loss, s);
    }
}

// ---------------------------------------------------------------------------
// K6: EMA codebook update + loss write
// ---------------------------------------------------------------------------
__global__ __launch_bounds__(256) void k_update(const float* __restrict__ emb,
                                                const float* __restrict__ csz,
                                                float* __restrict__ out) {
    int gtid = blockIdx.x * 256 + threadIdx.x;
    int k    = gtid >> 5;
    int lane = gtid & 31;

    float bcount = g_bins[k];
    if (lane == 0)
        out[OFF_CSZ + k] = csz[k] * 0.99f + 0.01f * bcount;

    bool  zero = (bcount == 0.0f);
    float bc   = zero ? 1.0f : bcount;
    float m    = g_esum[k * CDIM + lane] / bc;
    float ss   = m * m;
#pragma unroll
    for (int o = 16; o > 0; o >>= 1)
        ss += __shfl_xor_sync(0xffffffffu, ss, o);
    float en = m / fmaxf(sqrtf(ss), 1e-12f);

    float ev = emb[k * CDIM + lane];
    if (zero) en = ev;
    float v  = ev * 0.99f + 0.01f * en;
    float s2 = v * v;
#pragma unroll
    for (int o = 16; o > 0; o >>= 1)
        s2 += __shfl_xor_sync(0xffffffffu, s2, o);
    out[OFF_EMB + k * CDIM + lane] = v / fmaxf(sqrtf(s2), 1e-12f);

    if (gtid == 0)
        out[OFF_LOSS] = g_loss * (1.0f / (float)(N_VEC * CDIM));
}

// ---------------------------------------------------------------------------
extern "C" void kernel_launch(void* const* d_in, const int* in_sizes, int n_in,
                              void* d_out, int out_size) {
    const float* z   = (const float*)d_in[0];
    const float* emb = (const float*)d_in[1];
    const float* csz = (const float*)d_in[2];
    float* out = (float*)d_out;

    cudaFuncSetAttribute(k_mma, cudaFuncAttributeMaxDynamicSharedMemorySize, SMEM_TOTAL);

    k_prep_norm<<<N_VEC / 8, 256>>>(z);                      // launch 0
    k_prep_epk<<<ESPL_BLKS + TRNS_BLKS, 256>>>(emb);         // launch 1
    k_prep_zero<<<ZERO_BLKS, 256>>>();                       // launch 2
    dim3 grid_mma(N_VEC / 128, KSPL);
    k_mma<<<grid_mma, 256, SMEM_TOTAL>>>();                  // launch 3  <- ncu
    k_merge<<<N_VEC / 256, 256>>>();                         // launch 4
    k_fixup<<<FIX_SLOTS * 32, 128>>>();                      // launch 5
    k_scatter<<<(N_VEC * CDIM) / 256, 256>>>(emb, out);      // launch 6
    k_update<<<(N_TOK * CDIM) / 256, 256>>>(emb, csz, out);  // launch 7
}

// round 12
// speedup vs baseline: 4.0913x; 1.0297x over previous
#include <cuda_runtime.h>
#include <cstdint>

// ---------------------------------------------------------------------------
// NormEMAVectorQuantizer (sm_103a via compute_103) — round 12
// TF32 mma.sync screen (ILP-4, KSPL=8 -> 512 CTAs, ~3.5 CTAs/SM)
// + gap test + exact fp32 fixup.
//   out = concat( z_q[262144], loss[1], token_ids[8192],
//                 new_embedding[262144], new_cluster_sizes[8192] ) = 540673 f32
// ---------------------------------------------------------------------------

#define N_VEC   8192
#define N_TOK   8192
#define CDIM    32
#define KSPL    8
#define THRESH  2.0e-3f     // >= 2 * 2^-10 rigorous tf32 dot-error bound (unit vecs)

#define OFF_ZQ    0
#define OFF_LOSS  262144
#define OFF_TOK   262145
#define OFF_EMB   270337
#define OFF_CSZ   532481

// B layout: per code 40 words (32 tf32, fragment-pair reordered, +8 pad)
#define EPKW        40
#define CODE_BYTES  160
#define NB_CODES    128
#define STAGE_BYTES (NB_CODES * CODE_BYTES)   // 20480
#define SMEM_TOTAL  (2 * STAGE_BYTES)         // 40960

// scratch (__device__ globals; no allocations allowed)
__device__ float              g_zn[N_VEC * CDIM];
__device__ uint32_t           g_qpk[N_VEC * CDIM];     // tf32, dense
__device__ uint32_t           g_epk[N_TOK * EPKW];     // tf32, reordered
__device__ float              g_ekT[CDIM * N_TOK];     // fp32 codes, TRANSPOSED
__device__ unsigned long long g_t1[KSPL * N_VEC];      // packed (val|inv idx)
__device__ float              g_t2v[KSPL * N_VEC];     // runner-up value
__device__ unsigned long long g_key[N_VEC];
__device__ int                g_fix[N_VEC];
__device__ int                g_nfix;
__device__ float              g_bins[N_TOK];
__device__ float              g_esum[N_TOK * CDIM];
__device__ float              g_loss;

// ---------------- helpers ---------------------------------------------------
static __device__ __forceinline__ uint32_t smem_u32(const void* p) {
    uint32_t a;
    asm("{ .reg .u64 t; cvta.to.shared.u64 t, %1; cvt.u32.u64 %0, t; }" : "=r"(a) : "l"(p));
    return a;
}
static __device__ __forceinline__ unsigned int ordered_u32(float v) {
    unsigned int b = __float_as_uint(v);
    return (b & 0x80000000u) ? ~b : (b | 0x80000000u);
}
static __device__ __forceinline__ float unordered_f32(unsigned int u) {
    unsigned int b = (u & 0x80000000u) ? (u & 0x7fffffffu) : ~u;
    return __uint_as_float(b);
}
static __device__ __forceinline__ uint32_t to_tf32(float x) {
    uint32_t r;
    asm("cvt.rna.tf32.f32 %0, %1;" : "=r"(r) : "f"(x));
    return r;
}
static __device__ __forceinline__ int b_reorder(int c) {
    int kc = c >> 3, r = c & 7;
    return kc * 8 + ((r < 4) ? (r * 2) : ((r - 4) * 2 + 1));
}

#define MMA_TF32(D, Af, Bf)                                                   \
    asm volatile(                                                             \
        "mma.sync.aligned.m16n8k8.row.col.f32.tf32.tf32.f32 "                 \
        "{%0,%1,%2,%3}, {%4,%5,%6,%7}, {%8,%9}, {%0,%1,%2,%3};"               \
        : "+f"((D)[0]), "+f"((D)[1]), "+f"((D)[2]), "+f"((D)[3])              \
        : "r"((Af)[0]), "r"((Af)[1]), "r"((Af)[2]), "r"((Af)[3]),             \
          "r"((Bf)[0]), "r"((Bf)[1]))

// ---------------------------------------------------------------------------
// K1a: L2norm(z) -> g_zn + tf32 pack (1024 blocks)
// ---------------------------------------------------------------------------
__global__ __launch_bounds__(256) void k_prep_norm(const float* __restrict__ z) {
    int warp = threadIdx.x >> 5;
    int lane = threadIdx.x & 31;                 // channel c
    int n    = blockIdx.x * 8 + warp;
    int b    = n >> 8, hw = n & 255;
    float v  = z[b * (CDIM * 256) + lane * 256 + hw];
    float ss = v * v;
#pragma unroll
    for (int o = 16; o > 0; o >>= 1)
        ss += __shfl_xor_sync(0xffffffffu, ss, o);
    float inv = 1.0f / fmaxf(sqrtf(ss), 1e-12f);
    float x = v * inv;
    g_zn[n * CDIM + lane]  = x;
    g_qpk[n * CDIM + lane] = to_tf32(x);
}

// ---------------------------------------------------------------------------
// K1b: embedding tf32 reorder-pack (1024 blocks) + fp32 transpose (32 blocks)
// ---------------------------------------------------------------------------
#define ESPL_BLKS 1024
#define TRNS_BLKS 32
__global__ __launch_bounds__(256) void k_prep_epk(const float* __restrict__ emb) {
    __shared__ float tile[256][33];
    if (blockIdx.x < ESPL_BLKS) {
        int i = blockIdx.x * 256 + threadIdx.x;   // 0..262143
        int r = i >> 5, c = i & 31;
        g_epk[r * EPKW + b_reorder(c)] = to_tf32(emb[i]);
    } else {
        int j = blockIdx.x - ESPL_BLKS;
        int rbase = j * 256;
#pragma unroll 4
        for (int jj = 0; jj < 32; jj++) {
            int idx = jj * 256 + threadIdx.x;     // coalesced read
            tile[idx >> 5][idx & 31] = emb[rbase * 32 + idx];
        }
        __syncthreads();
#pragma unroll
        for (int jj = 0; jj < 4; jj++) {
            int c = jj * 8 + (threadIdx.x >> 5);
#pragma unroll
            for (int inner = 0; inner < 8; inner++) {
                int r = inner * 32 + (threadIdx.x & 31);
                g_ekT[c * N_TOK + rbase + r] = tile[r][c];   // coalesced write
            }
        }
    }
}

// ---------------------------------------------------------------------------
// K1c: zero scratch
// ---------------------------------------------------------------------------
#define ZERO_ITEMS (N_TOK * CDIM + N_TOK)
#define ZERO_BLKS ((ZERO_ITEMS + 255) / 256)
__global__ __launch_bounds__(256) void k_prep_zero() {
    int i = blockIdx.x * 256 + threadIdx.x;
    if (i < N_TOK * CDIM) g_esum[i] = 0.0f;
    else if (i < ZERO_ITEMS) g_bins[i - N_TOK * CDIM] = 0.0f;
    if (i == 0) { g_loss = 0.0f; g_nfix = 0; }
}

// ---------------------------------------------------------------------------
// K2: TF32 mma.sync screen, ILP-4 chains, grid (64, 8) = 512 CTAs
// (~3.5 CTAs/SM -> ~28 warps/SM). Warp = 16 queries; CTA = 128 queries x
// 1024 codes (8 stage iterations of 128 codes).
// ---------------------------------------------------------------------------
__global__ __launch_bounds__(256) void k_mma() {
    extern __shared__ uint32_t smem[];
    uint32_t sbase = smem_u32(smem);
    int tid = threadIdx.x, wid = tid >> 5, lane = tid & 31;
    int g4 = lane >> 2, l4 = lane & 3;
    int qb    = blockIdx.x * 128 + wid * 16;
    int kbase = blockIdx.y * (N_TOK / KSPL);

    uint32_t A[4][4];
    {
        const uint32_t* q0 = g_qpk + (qb + g4) * CDIM;
        const uint32_t* q8 = g_qpk + (qb + g4 + 8) * CDIM;
#pragma unroll
        for (int kc = 0; kc < 4; kc++) {
            int w = kc * 8 + l4;
            A[kc][0] = q0[w];
            A[kc][1] = q8[w];
            A[kc][2] = q0[w + 4];
            A[kc][3] = q8[w + 4];
        }
    }

    float v1a = -3.4e38f, v2a = -3.4e38f; int k1a = 0;
    float v1b = -3.4e38f, v2b = -3.4e38f; int k1b = 0;

    {
        const char* src = (const char*)g_epk + (size_t)kbase * CODE_BYTES;
#pragma unroll
        for (int j = 0; j < 5; j++) {
            int idx = tid + j * 256;
            asm volatile("cp.async.ca.shared.global [%0], [%1], 16;"
                         :: "r"(sbase + idx * 16), "l"(src + idx * 16) : "memory");
        }
        asm volatile("cp.async.commit_group;" ::: "memory");
    }

    for (int nb = 0; nb < (N_TOK / KSPL) / NB_CODES; nb++) {
        asm volatile("cp.async.wait_group 0;" ::: "memory");
        __syncthreads();
        if (nb + 1 < (N_TOK / KSPL) / NB_CODES) {
            const char* src = (const char*)g_epk +
                              (size_t)(kbase + (nb + 1) * NB_CODES) * CODE_BYTES;
            uint32_t dst = sbase + ((nb + 1) & 1) * STAGE_BYTES;
#pragma unroll
            for (int j = 0; j < 5; j++) {
                int idx = tid + j * 256;
                asm volatile("cp.async.ca.shared.global [%0], [%1], 16;"
                             :: "r"(dst + idx * 16), "l"(src + idx * 16) : "memory");
            }
            asm volatile("cp.async.commit_group;" ::: "memory");
        }

        const uint32_t* buf = smem + (nb & 1) * (STAGE_BYTES / 4);

#pragma unroll 1
        for (int nt = 0; nt < NB_CODES / 8; nt += 4) {
            const uint32_t* r0 = buf + (nt * 8 + g4) * EPKW + l4 * 2;
            float D0[4] = {0.f, 0.f, 0.f, 0.f};
            float D1[4] = {0.f, 0.f, 0.f, 0.f};
            float D2[4] = {0.f, 0.f, 0.f, 0.f};
            float D3[4] = {0.f, 0.f, 0.f, 0.f};
#pragma unroll
            for (int kc = 0; kc < 4; kc++) {
                uint2 b0 = *(const uint2*)(r0 + kc * 8);
                uint2 b1 = *(const uint2*)(r0 + 8  * EPKW + kc * 8);
                uint2 b2 = *(const uint2*)(r0 + 16 * EPKW + kc * 8);
                uint2 b3 = *(const uint2*)(r0 + 24 * EPKW + kc * 8);
                uint32_t B0[2] = {b0.x, b0.y};
                uint32_t B1[2] = {b1.x, b1.y};
                uint32_t B2[2] = {b2.x, b2.y};
                uint32_t B3[2] = {b3.x, b3.y};
                MMA_TF32(D0, A[kc], B0);
                MMA_TF32(D1, A[kc], B1);
                MMA_TF32(D2, A[kc], B2);
                MMA_TF32(D3, A[kc], B3);
            }

            int c0 = kbase + nb * NB_CODES + nt * 8 + l4 * 2;
            {
                float m0 = fmaxf(D0[0], D0[1]);
                float m1 = fmaxf(D1[0], D1[1]);
                float m2 = fmaxf(D2[0], D2[1]);
                float m3 = fmaxf(D3[0], D3[1]);
                float vm = fmaxf(fmaxf(m0, m1), fmaxf(m2, m3));
                if (vm > v1a) {
                    float sec; int kk;
                    if (m0 == vm) {
                        sec = fmaxf(fminf(D0[0], D0[1]), fmaxf(m1, fmaxf(m2, m3)));
                        kk = (D0[0] == vm) ? c0 : c0 + 1;
                    } else if (m1 == vm) {
                        sec = fmaxf(fminf(D1[0], D1[1]), fmaxf(m0, fmaxf(m2, m3)));
                        kk = (D1[0] == vm) ? c0 + 8 : c0 + 9;
                    } else if (m2 == vm) {
                        sec = fmaxf(fminf(D2[0], D2[1]), fmaxf(m0, fmaxf(m1, m3)));
                        kk = (D2[0] == vm) ? c0 + 16 : c0 + 17;
                    } else {
                        sec = fmaxf(fminf(D3[0], D3[1]), fmaxf(m0, fmaxf(m1, m2)));
                        kk = (D3[0] == vm) ? c0 + 24 : c0 + 25;
                    }
                    v2a = fmaxf(fmaxf(v2a, v1a), sec);
                    v1a = vm; k1a = kk;
                } else {
                    v2a = fmaxf(v2a, vm);
                }
            }
            {
                float m0 = fmaxf(D0[2], D0[3]);
                float m1 = fmaxf(D1[2], D1[3]);
                float m2 = fmaxf(D2[2], D2[3]);
                float m3 = fmaxf(D3[2], D3[3]);
                float vm = fmaxf(fmaxf(m0, m1), fmaxf(m2, m3));
                if (vm > v1b) {
                    float sec; int kk;
                    if (m0 == vm) {
                        sec = fmaxf(fminf(D0[2], D0[3]), fmaxf(m1, fmaxf(m2, m3)));
                        kk = (D0[2] == vm) ? c0 : c0 + 1;
                    } else if (m1 == vm) {
                        sec = fmaxf(fminf(D1[2], D1[3]), fmaxf(m0, fmaxf(m2, m3)));
                        kk = (D1[2] == vm) ? c0 + 8 : c0 + 9;
                    } else if (m2 == vm) {
                        sec = fmaxf(fminf(D2[2], D2[3]), fmaxf(m0, fmaxf(m1, m3)));
                        kk = (D2[2] == vm) ? c0 + 16 : c0 + 17;
                    } else {
                        sec = fmaxf(fminf(D3[2], D3[3]), fmaxf(m0, fmaxf(m1, m2)));
                        kk = (D3[2] == vm) ? c0 + 24 : c0 + 25;
                    }
                    v2b = fmaxf(fmaxf(v2b, v1b), sec);
                    v1b = vm; k1b = kk;
                } else {
                    v2b = fmaxf(v2b, vm);
                }
            }
        }
    }

#pragma unroll
    for (int d = 1; d < 4; d <<= 1) {
        float ov1; int ok1; float ov2;
        ov1 = __shfl_xor_sync(0xffffffffu, v1a, d);
        ok1 = __shfl_xor_sync(0xffffffffu, k1a, d);
        ov2 = __shfl_xor_sync(0xffffffffu, v2a, d);
        {
            bool take = (ov1 > v1a) || (ov1 == v1a && ok1 < k1a);
            float lose = take ? v1a : ov1;
            v2a = fmaxf(fmaxf(v2a, ov2), lose);
            if (take) { v1a = ov1; k1a = ok1; }
        }
        ov1 = __shfl_xor_sync(0xffffffffu, v1b, d);
        ok1 = __shfl_xor_sync(0xffffffffu, k1b, d);
        ov2 = __shfl_xor_sync(0xffffffffu, v2b, d);
        {
            bool take = (ov1 > v1b) || (ov1 == v1b && ok1 < k1b);
            float lose = take ? v1b : ov1;
            v2b = fmaxf(fmaxf(v2b, ov2), lose);
            if (take) { v1b = ov1; k1b = ok1; }
        }
    }
    if (l4 == 0) {
        int q = qb + g4;
        int sp = blockIdx.y;
        g_t1[sp * N_VEC + q] =
            ((unsigned long long)ordered_u32(v1a) << 32) |
            (unsigned int)(N_TOK - 1 - k1a);
        g_t2v[sp * N_VEC + q] = v2a;
        g_t1[sp * N_VEC + q + 8] =
            ((unsigned long long)ordered_u32(v1b) << 32) |
            (unsigned int)(N_TOK - 1 - k1b);
        g_t2v[sp * N_VEC + q + 8] = v2b;
    }
}

// ---------------------------------------------------------------------------
// K3: merge KSPL splits' top-2, gap test, build fixup list
// ---------------------------------------------------------------------------
__global__ __launch_bounds__(256) void k_merge() {
    int n = blockIdx.x * 256 + threadIdx.x;
    unsigned long long win = 0ull;
    float v2 = -3.4e38f;
#pragma unroll
    for (int s = 0; s < KSPL; s++) {
        unsigned long long t = g_t1[s * N_VEC + n];
        float tv2 = g_t2v[s * N_VEC + n];
        if (t > win) {
            v2 = fmaxf(v2, unordered_f32((unsigned int)(win >> 32)));
            win = t;
        } else {
            v2 = fmaxf(v2, unordered_f32((unsigned int)(t >> 32)));
        }
        v2 = fmaxf(v2, tv2);
    }
    float v1 = unordered_f32((unsigned int)(win >> 32));
    if (v1 - v2 < THRESH) {
        g_key[n] = 0ull;
        int i = atomicAdd(&g_nfix, 1);
        g_fix[i] = n;
    } else {
        g_key[n] = win;
    }
}

// ---------------------------------------------------------------------------
// K4: exact fp32 rescan for flagged queries (pairs -> 4 FMA chains).
// ---------------------------------------------------------------------------
#define FIX_SLOTS 128
__global__ __launch_bounds__(128) void k_fixup() {
    __shared__ int   qid[8];
    __shared__ float zq[8][32];
    __shared__ unsigned long long wbest[8][4];
    int cnt = g_nfix;
    int chunk = blockIdx.x & 31;
    int slot  = blockIdx.x >> 5;
    if (slot * 8 >= cnt) return;
    int t = threadIdx.x, wd = t >> 5, ln = t & 31;

    int ka = chunk * 256 + t;
    int kb = ka + 128;
    float ra[CDIM], rb[CDIM];
#pragma unroll
    for (int c = 0; c < CDIM; c++) {
        ra[c] = g_ekT[c * N_TOK + ka];
        rb[c] = g_ekT[c * N_TOK + kb];
    }

    for (int qg = slot * 8; qg < cnt; qg += FIX_SLOTS * 8) {
        int nq = cnt - qg;
        if (nq > 8) nq = 8;
        if (t < 8) qid[t] = (t < nq) ? g_fix[qg + t] : -1;
        __syncthreads();
#pragma unroll
        for (int j = 0; j < 2; j++) {
            int idx = t + j * 128;
            int q = idx >> 5, c = idx & 31;
            int n = qid[q];
            zq[q][c] = (n >= 0) ? g_zn[n * CDIM + c] : 0.0f;
        }
        __syncthreads();

#pragma unroll 1
        for (int q = 0; q < 8; q += 2) {
            float sa0 = 0.f, sa1 = 0.f, sb0 = 0.f, sb1 = 0.f;
#pragma unroll
            for (int c = 0; c < CDIM; c++) {
                float za = zq[q][c];
                float zb = zq[q + 1][c];
                sa0 = fmaf(za, ra[c], sa0);
                sa1 = fmaf(za, rb[c], sa1);
                sb0 = fmaf(zb, ra[c], sb0);
                sb1 = fmaf(zb, rb[c], sb1);
            }
            unsigned long long keyA, keyB, tmp;
            keyA = ((unsigned long long)ordered_u32(sa0) << 32) |
                   (unsigned int)(N_TOK - 1 - ka);
            tmp  = ((unsigned long long)ordered_u32(sa1) << 32) |
                   (unsigned int)(N_TOK - 1 - kb);
            if (tmp > keyA) keyA = tmp;
            keyB = ((unsigned long long)ordered_u32(sb0) << 32) |
                   (unsigned int)(N_TOK - 1 - ka);
            tmp  = ((unsigned long long)ordered_u32(sb1) << 32) |
                   (unsigned int)(N_TOK - 1 - kb);
            if (tmp > keyB) keyB = tmp;
#pragma unroll
            for (int o = 16; o > 0; o >>= 1) {
                unsigned long long oa = __shfl_xor_sync(0xffffffffu, keyA, o);
                unsigned long long ob = __shfl_xor_sync(0xffffffffu, keyB, o);
                if (oa > keyA) keyA = oa;
                if (ob > keyB) keyB = ob;
            }
            if (ln == 0) { wbest[q][wd] = keyA; wbest[q + 1][wd] = keyB; }
        }
        __syncthreads();
        if (t < 8 && qid[t] >= 0) {
            unsigned long long b = wbest[t][0];
#pragma unroll
            for (int w = 1; w < 4; w++) if (wbest[t][w] > b) b = wbest[t][w];
            atomicMax(&g_key[qid[t]], b);
        }
        __syncthreads();
    }
}

// ---------------------------------------------------------------------------
// K5: scatter epilogue over 262144 threads
// ---------------------------------------------------------------------------
__global__ __launch_bounds__(256) void k_scatter(const float* __restrict__ emb,
                                                 float* __restrict__ out) {
    __shared__ float red[8];
    int g  = blockIdx.x * 256 + threadIdx.x;
    int b  = g >> 13;
    int c  = (g >> 8) & 31;
    int hw = g & 255;
    int n  = b * 256 + hw;

    unsigned long long key = g_key[n];
    int bi = (N_TOK - 1) - (int)(unsigned int)(key & 0xffffffffu);

    float ev = emb[bi * CDIM + c];
    float zv = g_zn[n * CDIM + c];
    out[OFF_ZQ + g] = ev;
    if (c == 0) {
        out[OFF_TOK + n] = (float)bi;
        atomicAdd(&g_bins[bi], 1.0f);
    }
    atomicAdd(&g_esum[bi * CDIM + c], zv);

    float d = ev - zv;
    float lsum = d * d;
#pragma unroll
    for (int o = 16; o > 0; o >>= 1)
        lsum += __shfl_xor_sync(0xffffffffu, lsum, o);
    if ((threadIdx.x & 31) == 0) red[threadIdx.x >> 5] = lsum;
    __syncthreads();
    if (threadIdx.x == 0) {
        float s = 0.0f;
#pragma unroll
        for (int w = 0; w < 8; w++) s += red[w];
        atomicAdd(&g_loss, s);
    }
}

// ---------------------------------------------------------------------------
// K6: EMA codebook update + loss write
// ---------------------------------------------------------------------------
__global__ __launch_bounds__(256) void k_update(const float* __restrict__ emb,
                                                const float* __restrict__ csz,
                                                float* __restrict__ out) {
    int gtid = blockIdx.x * 256 + threadIdx.x;
    int k    = gtid >> 5;
    int lane = gtid & 31;

    float bcount = g_bins[k];
    if (lane == 0)
        out[OFF_CSZ + k] = csz[k] * 0.99f + 0.01f * bcount;

    bool  zero = (bcount == 0.0f);
    float bc   = zero ? 1.0f : bcount;
    float m    = g_esum[k * CDIM + lane] / bc;
    float ss   = m * m;
#pragma unroll
    for (int o = 16; o > 0; o >>= 1)
        ss += __shfl_xor_sync(0xffffffffu, ss, o);
    float en = m / fmaxf(sqrtf(ss), 1e-12f);

    float ev = emb[k * CDIM + lane];
    if (zero) en = ev;
    float v  = ev * 0.99f + 0.01f * en;
    float s2 = v * v;
#pragma unroll
    for (int o = 16; o > 0; o >>= 1)
        s2 += __shfl_xor_sync(0xffffffffu, s2, o);
    out[OFF_EMB + k * CDIM + lane] = v / fmaxf(sqrtf(s2), 1e-12f);

    if (gtid == 0)
        out[OFF_LOSS] = g_loss * (1.0f / (float)(N_VEC * CDIM));
}

// ---------------------------------------------------------------------------
extern "C" void kernel_launch(void* const* d_in, const int* in_sizes, int n_in,
                              void* d_out, int out_size) {
    const float* z   = (const float*)d_in[0];
    const float* emb = (const float*)d_in[1];
    const float* csz = (const float*)d_in[2];
    float* out = (float*)d_out;

    cudaFuncSetAttribute(k_mma, cudaFuncAttributeMaxDynamicSharedMemorySize, SMEM_TOTAL);

    k_prep_norm<<<N_VEC / 8, 256>>>(z);                      // launch 0
    k_prep_epk<<<ESPL_BLKS + TRNS_BLKS, 256>>>(emb);         // launch 1
    k_prep_zero<<<ZERO_BLKS, 256>>>();                       // launch 2
    dim3 grid_mma(N_VEC / 128, KSPL);
    k_mma<<<grid_mma, 256, SMEM_TOTAL>>>();                  // launch 3  <- ncu
    k_merge<<<N_VEC / 256, 256>>>();                         // launch 4
    k_fixup<<<FIX_SLOTS * 32, 128>>>();                      // launch 5
    k_scatter<<<(N_VEC * CDIM) / 256, 256>>>(emb, out);      // launch 6
    k_update<<<(N_TOK * CDIM) / 256, 256>>>(emb, csz, out);  // launch 7
}